// round 14
// baseline (speedup 1.0000x reference)
#include <cuda_runtime.h>
#include <cuda_fp16.h>
#include <cstdint>
#include <math.h>

#define DD 128
#define NMAX 100000
#define EMAX 1600000
#define LUTN 2048
#define NNL 8192
#define LNEPS 1e-5f
#define TSTRIDE 136                    // fp16 elems per smem tile row (bank-safe)
#define TBYTES (128 * TSTRIDE * 2)     // 34816 B per 128x128 fp16 tile
#define TU4 (TBYTES / 16)              // 2176 uint4 per tile

typedef unsigned long long ull;

// ---------------- scratch (static device globals) ---------------------------
__device__ __half g_ax[NMAX * DD];     // silu(x @ agg_W + b), fp16
__device__ __half g_agg[NMAX * DD];    // mean-aggregated messages, fp16
__device__ int    g_cnti[NMAX];
__device__ int    g_rows[NMAX + 1];
__device__ int    g_cur[NMAX];
__device__ int    g_csr_src[EMAX];
__device__ float  g_csr_w[EMAX];
__device__ float2 g_lut[LUTN + 1];     // interp sigmoid {s_i - i*d_i, d_i}
__device__ float  g_nn[NNL];           // NN sigmoid table (gate)
// pre-split transposed fp16 weights, [N rows][K cols] stride TSTRIDE:
// mats: 0=aggW, 1=uW1[:128], 2=uW1[128:], 3=uW2, 4=resW
__device__ __align__(16) unsigned char g_wt[5][2][TBYTES];

// edge-MLP weights in constant memory (uniform access -> no LDS traffic)
__constant__ ull c_w1s[4][64];   // W1 row-major 4x128 floats as 64 pairs per row
__constant__ ull c_b1s[64];
__constant__ ull c_w2s[64];

// ---------------- packed f32x2 helpers (gate kernel) --------------------------
__device__ __forceinline__ ull pack_dup(float a) {
    unsigned int au = __float_as_uint(a);
    ull r; asm("mov.b64 %0, {%1, %1};" : "=l"(r) : "r"(au)); return r;
}
__device__ __forceinline__ ull pack2(float lo, float hi) {
    ull r; asm("mov.b64 %0, {%1, %2};" : "=l"(r) : "r"(__float_as_uint(lo)), "r"(__float_as_uint(hi))); return r;
}
__device__ __forceinline__ void fma2(ull& d, ull a, ull b) {
    asm("fma.rn.f32x2 %0, %1, %2, %0;" : "+l"(d) : "l"(a), "l"(b));
}
__device__ __forceinline__ ull mul2(ull a, ull b) {
    ull r; asm("mul.rn.f32x2 %0, %1, %2;" : "=l"(r) : "l"(a), "l"(b)); return r;
}
__device__ __forceinline__ void unpack2(ull v, float& lo, float& hi) {
    unsigned int l, h;
    asm("mov.b64 {%0, %1}, %2;" : "=r"(l), "=r"(h) : "l"(v));
    lo = __uint_as_float(l); hi = __uint_as_float(h);
}

// ---------------- sigmoid LUT --------------------------------------------------
__device__ __forceinline__ float lut_sigma_g(float z) {
    float t = fminf(fmaxf(fmaf(z, 128.f, 1024.f), 0.f), 2047.99f);
    float2 e = __ldg(&g_lut[(int)t]);
    return fmaf(e.y, t, e.x);
}

// ---------------- fp16 mma.sync (sm_70+ baseline) ------------------------------
#define MMA4(c, a, b0, b1) \
    asm volatile("mma.sync.aligned.m16n8k16.row.col.f32.f16.f16.f32 " \
        "{%0,%1,%2,%3}, {%4,%5,%6,%7}, {%8,%9}, {%0,%1,%2,%3};" \
        : "+f"((c)[0]), "+f"((c)[1]), "+f"((c)[2]), "+f"((c)[3]) \
        : "r"((a)[0]), "r"((a)[1]), "r"((a)[2]), "r"((a)[3]), "r"(b0), "r"(b1))

// s-outer / nt-inner GEMM span, 2-term (A fp16, W split hi+lo fp16)
__device__ __forceinline__ void mma_span(float* acc,
    const char* Ah, const char* Wh, const char* Wl,
    int s0, int s1, int warp, int g, int tig) {
    const char* arow = Ah + ((warp * 16 + g) * TSTRIDE + tig * 2) * 2;
#pragma unroll
    for (int s = s0; s < s1; s++) {
        unsigned int afH[4];
        const char* pa = arow + s * 32;
        afH[0] = *(const unsigned int*)(pa);
        afH[1] = *(const unsigned int*)(pa + 8 * TSTRIDE * 2);
        afH[2] = *(const unsigned int*)(pa + 16);
        afH[3] = *(const unsigned int*)(pa + 8 * TSTRIDE * 2 + 16);
        int kb = s * 32;
#pragma unroll
        for (int nt = 0; nt < 16; nt++) {
            const char* bh = Wh + (nt * 8 + g) * (TSTRIDE * 2) + tig * 4 + kb;
            const char* bl = Wl + (nt * 8 + g) * (TSTRIDE * 2) + tig * 4 + kb;
            unsigned int b0h = *(const unsigned int*)(bh);
            unsigned int b1h = *(const unsigned int*)(bh + 16);
            unsigned int b0l = *(const unsigned int*)(bl);
            unsigned int b1l = *(const unsigned int*)(bl + 16);
            float* c = acc + nt * 4;
            MMA4(c, afH, b0h, b1h);
            MMA4(c, afH, b0l, b1l);
        }
    }
}

// fp32 [128 rows] tile -> fp16 smem tile (256 threads)
__device__ __forceinline__ void conv_tileH(char* hi, const float* __restrict__ src,
                                           int row0, int n, int tid) {
#pragma unroll
    for (int i = 0; i < 8; i++) {
        int ch = tid + 256 * i;
        int row = ch >> 4, part = ch & 15;
        int gr = row0 + row;
        float4 v0 = make_float4(0.f, 0.f, 0.f, 0.f);
        float4 v1 = make_float4(0.f, 0.f, 0.f, 0.f);
        if (gr < n) {
            const float4* p = (const float4*)(src + gr * DD + part * 8);
            v0 = __ldg(p);
            v1 = __ldg(p + 1);
        }
        float s[8];
        s[0] = v0.x; s[1] = v0.y; s[2] = v0.z; s[3] = v0.w;
        s[4] = v1.x; s[5] = v1.y; s[6] = v1.z; s[7] = v1.w;
        union { uint4 u; __half h[8]; } H;
#pragma unroll
        for (int j = 0; j < 8; j++) H.h[j] = __float2half_rn(s[j]);
        int off = (row * TSTRIDE + part * 8) * 2;
        *(uint4*)(hi + off) = H.u;
    }
}

// fp16 [128 rows] tile -> fp16 smem tile (plain strided copy, 256 threads)
__device__ __forceinline__ void copy_tileH(char* hi, const __half* __restrict__ src,
                                           int row0, int n, int tid) {
#pragma unroll
    for (int i = 0; i < 8; i++) {
        int ch = tid + 256 * i;
        int row = ch >> 4, part = ch & 15;
        int gr = row0 + row;
        uint4 v = make_uint4(0u, 0u, 0u, 0u);
        if (gr < n) v = __ldg((const uint4*)(src + gr * DD + part * 8));
        int off = (row * TSTRIDE + part * 8) * 2;
        *(uint4*)(hi + off) = v;
    }
}

// full weight tile pair global -> smem (256 threads)
__device__ __forceinline__ void load_wt256(char* hi, char* lo,
                                           const unsigned char* gh,
                                           const unsigned char* gl, int tid) {
#pragma unroll
    for (int i = 0; i < 9; i++) {
        int idx = tid + 256 * i;
        if (idx < TU4) {
            ((uint4*)hi)[idx] = __ldg((const uint4*)gh + idx);
            ((uint4*)lo)[idx] = __ldg((const uint4*)gl + idx);
        }
    }
}

// register prefetch of a weight tile pair (issue LDGs; consume later)
__device__ __forceinline__ void pf_load(uint4* pfh, uint4* pfl,
                                        const unsigned char* gh,
                                        const unsigned char* gl, int tid) {
#pragma unroll
    for (int i = 0; i < 9; i++) {
        int idx = tid + 256 * i;
        if (idx < TU4) {
            pfh[i] = __ldg((const uint4*)gh + idx);
            pfl[i] = __ldg((const uint4*)gl + idx);
        }
    }
}
__device__ __forceinline__ void pf_store(char* hi, char* lo,
                                         const uint4* pfh, const uint4* pfl, int tid) {
#pragma unroll
    for (int i = 0; i < 9; i++) {
        int idx = tid + 256 * i;
        if (idx < TU4) {
            ((uint4*)hi)[idx] = pfh[i];
            ((uint4*)lo)[idx] = pfl[i];
        }
    }
}

// ---------------- LUT build + count zero ---------------------------------------
__global__ void k_lut_zcnt(int n) {
    int stride = blockDim.x * gridDim.x;
    for (int i = threadIdx.x + blockIdx.x * blockDim.x; i <= LUTN; i += stride) {
        float z0 = -8.f + (float)i * (16.f / LUTN);
        float z1 = z0 + (16.f / LUTN);
        float s0 = 1.f / (1.f + expf(-z0));
        float s1 = 1.f / (1.f + expf(-z1));
        float d  = s1 - s0;
        g_lut[i] = make_float2(s0 - (float)i * d, d);
    }
    for (int i = threadIdx.x + blockIdx.x * blockDim.x; i < NNL; i += stride) {
        float z = -8.f + ((float)i + 0.5f) * (16.f / NNL);
        g_nn[i] = 1.f / (1.f + expf(-z));
    }
    for (int i = threadIdx.x + blockIdx.x * blockDim.x; i < n; i += stride)
        g_cnti[i] = 0;
}

// ---------------- fused: degree count + weight prep -----------------------------
__global__ void k_count_wprep(const int* __restrict__ ei, int E,
                              const float* __restrict__ aggW, const float* __restrict__ uW1,
                              const float* __restrict__ uW2, const float* __restrict__ resW) {
    int tid0 = threadIdx.x + blockIdx.x * blockDim.x;
    int stride = blockDim.x * gridDim.x;
    for (int idx = tid0; idx < 5 * 16384; idx += stride) {
        int mat = idx >> 14, e = idx & 16383;
        int k = e >> 7, col = e & 127;
        const float* src = (mat == 0) ? aggW : (mat == 1) ? uW1 : (mat == 2) ? (uW1 + 16384)
                         : (mat == 3) ? uW2 : resW;
        float v = __ldg(&src[k * DD + col]);
        __half h = __float2half_rn(v);
        __half l = __float2half_rn(v - __half2float(h));
        int off = (col * TSTRIDE + k) * 2;
        *(__half*)(&g_wt[mat][0][off]) = h;
        *(__half*)(&g_wt[mat][1][off]) = l;
    }
    for (int i = tid0; i < E; i += stride)
        atomicAdd(&g_cnti[__ldg(&ei[E + i])], 1);
}

__global__ void __launch_bounds__(1024)
k_scan_fused(int n, int E) {
    __shared__ int sh[1024];
    int t = threadIdx.x;
    int len = (n + 1023) / 1024;
    int s = t * len;
    int e = min(s + len, n);
    int sum = 0;
    for (int i = s; i < e; i++) sum += g_cnti[i];
    sh[t] = sum;
    __syncthreads();
    for (int o = 1; o < 1024; o <<= 1) {
        int u = (t >= o) ? sh[t - o] : 0;
        __syncthreads();
        sh[t] += u;
        __syncthreads();
    }
    int excl = sh[t] - sum;
    for (int i = s; i < e; i++) {
        int c = g_cnti[i];
        g_rows[i] = excl;
        g_cur[i]  = excl;
        excl += c;
    }
    if (t == 0) g_rows[n] = E;
}

// ---------------- edge gate + CSR permute (thread per edge, const weights) -------
__global__ void __launch_bounds__(256)
k_gate(const int* __restrict__ ei, const float* __restrict__ ea,
       const float* __restrict__ b2p, int E) {
    __shared__ float nn[NNL];
    for (int i = threadIdx.x; i < NNL; i += blockDim.x) nn[i] = g_nn[i];
    __syncthreads();

    float b2v = __ldg(b2p);
    int stride = blockDim.x * gridDim.x;
    int e0 = threadIdx.x + blockIdx.x * blockDim.x;

    int src = 0, dst = 0;
    float4 a = make_float4(0.f, 0.f, 0.f, 0.f);
    if (e0 < E) {
        src = __ldg(&ei[e0]);
        dst = __ldg(&ei[E + e0]);
        a   = __ldg((const float4*)(ea + 4 * e0));
    }

    for (int e = e0; e < E; ) {
        int srcC = src, dstC = dst;
        float4 aC = a;
        int eN = e + stride;
        if (eN < E) {
            src = __ldg(&ei[eN]);
            dst = __ldg(&ei[E + eN]);
            a   = __ldg((const float4*)(ea + 4 * eN));
        }

        ull ax = pack_dup(aC.x), ay = pack_dup(aC.y);
        ull az = pack_dup(aC.z), aw = pack_dup(aC.w);
        ull dot2 = 0ull;
#pragma unroll 16
        for (int c2 = 0; c2 < 64; c2++) {
            ull zz = c_b1s[c2];
            fma2(zz, ax, c_w1s[0][c2]);
            fma2(zz, ay, c_w1s[1][c2]);
            fma2(zz, az, c_w1s[2][c2]);
            fma2(zz, aw, c_w1s[3][c2]);
            float z0, z1;
            unpack2(zz, z0, z1);
            float t0 = fminf(fmaxf(fmaf(z0, 512.f, 4096.f), 0.f), 8191.f);
            float t1 = fminf(fmaxf(fmaf(z1, 512.f, 4096.f), 0.f), 8191.f);
            ull zs = mul2(zz, pack2(nn[(int)t0], nn[(int)t1]));
            fma2(dot2, zs, c_w2s[c2]);
        }
        float d0, d1;
        unpack2(dot2, d0, d1);
        float zg = d0 + d1 + b2v;
        float tg = fminf(fmaxf(fmaf(zg, 512.f, 4096.f), 0.f), 8191.f);
        float ew = nn[(int)tg];

        int pos = atomicAdd(&g_cur[dstC], 1);
        g_csr_src[pos] = srcC;
        g_csr_w[pos]   = ew;
        e = eN;
    }
}

// ---------------- gather (warp per node, fp16 messages) --------------------------
__device__ __forceinline__ void acc_half4(float4& a, unsigned int lo, unsigned int hi, float w) {
    float2 f0 = __half22float2(*(__half2*)&lo);
    float2 f1 = __half22float2(*(__half2*)&hi);
    a.x = fmaf(w, f0.x, a.x); a.y = fmaf(w, f0.y, a.y);
    a.z = fmaf(w, f1.x, a.z); a.w = fmaf(w, f1.y, a.w);
}

__global__ void __launch_bounds__(256)
k_gather(int n) {
    int lane  = threadIdx.x & 31;
    int w     = (blockIdx.x * blockDim.x + threadIdx.x) >> 5;
    int nwarp = (gridDim.x * blockDim.x) >> 5;

    for (int i = w; i < n; i += nwarp) {
        int s = g_rows[i], e = g_rows[i + 1];
        float4 a0 = make_float4(0.f, 0.f, 0.f, 0.f);
        float4 a1 = make_float4(0.f, 0.f, 0.f, 0.f);
        float4 a2 = make_float4(0.f, 0.f, 0.f, 0.f);
        float4 a3 = make_float4(0.f, 0.f, 0.f, 0.f);
        int j = s;
        for (; j + 3 < e; j += 4) {
            int   s0 = __ldg(&g_csr_src[j]);
            int   s1 = __ldg(&g_csr_src[j + 1]);
            int   s2 = __ldg(&g_csr_src[j + 2]);
            int   s3 = __ldg(&g_csr_src[j + 3]);
            float w0 = __ldg(&g_csr_w[j]);
            float w1 = __ldg(&g_csr_w[j + 1]);
            float w2 = __ldg(&g_csr_w[j + 2]);
            float w3 = __ldg(&g_csr_w[j + 3]);
            uint2 v0 = __ldg((const uint2*)(g_ax + s0 * DD + lane * 4));
            uint2 v1 = __ldg((const uint2*)(g_ax + s1 * DD + lane * 4));
            uint2 v2 = __ldg((const uint2*)(g_ax + s2 * DD + lane * 4));
            uint2 v3 = __ldg((const uint2*)(g_ax + s3 * DD + lane * 4));
            acc_half4(a0, v0.x, v0.y, w0);
            acc_half4(a1, v1.x, v1.y, w1);
            acc_half4(a2, v2.x, v2.y, w2);
            acc_half4(a3, v3.x, v3.y, w3);
        }
        for (; j < e; j++) {
            int   s0 = __ldg(&g_csr_src[j]);
            float w0 = __ldg(&g_csr_w[j]);
            uint2 v0 = __ldg((const uint2*)(g_ax + s0 * DD + lane * 4));
            acc_half4(a0, v0.x, v0.y, w0);
        }
        float rv = 1.f / fmaxf((float)(e - s), 1.f);
        float ox = (a0.x + a1.x + a2.x + a3.x) * rv;
        float oy = (a0.y + a1.y + a2.y + a3.y) * rv;
        float oz = (a0.z + a1.z + a2.z + a3.z) * rv;
        float ow = (a0.w + a1.w + a2.w + a3.w) * rv;
        union { uint2 u; __half h[4]; } O;
        O.h[0] = __float2half_rn(ox); O.h[1] = __float2half_rn(oy);
        O.h[2] = __float2half_rn(oz); O.h[3] = __float2half_rn(ow);
        *(uint2*)(g_agg + i * DD + lane * 4) = O.u;
    }
}

// ---------------- K1 (HMMA fp16): g_ax = silu(x @ agg_W + b) ---------------------
// smem: bias 512 + AH + WH + WL = 512 + 3*34816 = 104960 -> 2 blocks/SM
__global__ void __launch_bounds__(256, 2)
k_agg_m(const float* __restrict__ x, const float* __restrict__ bias, int n) {
    extern __shared__ char sm[];
    const int O_B = 0, O_AH = 512, O_WH = O_AH + TBYTES, O_WL = O_WH + TBYTES;
    int tid = threadIdx.x;
    int row0 = blockIdx.x * 128;

    if (tid < 128) ((float*)(sm + O_B))[tid] = __ldg(&bias[tid]);
    conv_tileH(sm + O_AH, x, row0, n, tid);
    load_wt256(sm + O_WH, sm + O_WL, g_wt[0][0], g_wt[0][1], tid);
    __syncthreads();

    int lane = tid & 31, warp = tid >> 5;
    int g = lane >> 2, tig = lane & 3;

    float acc[64];
#pragma unroll
    for (int i = 0; i < 64; i++) acc[i] = 0.f;
    mma_span(acc, sm + O_AH, sm + O_WH, sm + O_WL, 0, 8, warp, g, tig);

    const float* bs = (const float*)(sm + O_B);
    int r_hi = row0 + warp * 16 + g;
    int r_lo = r_hi + 8;
#pragma unroll
    for (int nt = 0; nt < 16; nt++) {
        int c0 = nt * 8 + tig * 2;
        float b0 = bs[c0], b1v = bs[c0 + 1];
        if (r_hi < n) {
            float z0 = acc[nt * 4 + 0] + b0, z1 = acc[nt * 4 + 1] + b1v;
            __half2 v = __floats2half2_rn(z0 * lut_sigma_g(z0), z1 * lut_sigma_g(z1));
            *(__half2*)(g_ax + r_hi * DD + c0) = v;
        }
        if (r_lo < n) {
            float z0 = acc[nt * 4 + 2] + b0, z1 = acc[nt * 4 + 3] + b1v;
            __half2 v = __floats2half2_rn(z0 * lut_sigma_g(z0), z1 * lut_sigma_g(z1));
            *(__half2*)(g_ax + r_lo * DD + c0) = v;
        }
    }
}

// ---------------- fused update (HMMA fp16): pipelined 4 GEMMs + LN ---------------
// smem: params 2048 + XH, TH, WA(hi+lo), WB(hi+lo) = 2048 + 4*34816 = 141312
__global__ void __launch_bounds__(256)
k_upd12_m(const float* __restrict__ x,
          const float* __restrict__ b1, const float* __restrict__ b2,
          const float* __restrict__ lng, const float* __restrict__ lnb,
          float* __restrict__ out, int n) {
    extern __shared__ char sm[];
    const int O_B1 = 0, O_B2 = 512, O_LG = 1024, O_LB = 1536,
              O_XH = 2048, O_TH = O_XH + TBYTES,
              O_WA = O_TH + TBYTES, O_WB = O_WA + TBYTES;
    // W buffer layout: hi = first 64 n-rows? No — keep hi/lo as two half-size
    // regions inside each buffer: hi at +0, lo at +TBYTES/2 is wrong (tile is
    // full-size). Instead: WA holds hi of current, WB holds lo of current for
    // phase; we ping-pong PAIRS: (WA=hi,WB=lo) <-> reuse same buffers since
    // prefetch regs bridge the swap.
    int tid = threadIdx.x;
    int row0 = blockIdx.x * 128;

    if (tid < 128) {
        ((float*)(sm + O_B1))[tid] = __ldg(&b1[tid]);
        ((float*)(sm + O_B2))[tid] = __ldg(&b2[tid]);
        ((float*)(sm + O_LG))[tid] = __ldg(&lng[tid]);
        ((float*)(sm + O_LB))[tid] = __ldg(&lnb[tid]);
    }
    conv_tileH(sm + O_XH, x, row0, n, tid);
    copy_tileH(sm + O_TH, g_agg, row0, n, tid);
    load_wt256(sm + O_WA, sm + O_WB, g_wt[1][0], g_wt[1][1], tid);
    __syncthreads();

    int lane = tid & 31, warp = tid >> 5;
    int g = lane >> 2, tig = lane & 3;

    float acc[64];
#pragma unroll
    for (int i = 0; i < 64; i++) acc[i] = 0.f;

    uint4 pfh[9], pfl[9];

    // phase A: x @ W1a   (prefetch W1b during span)
    pf_load(pfh, pfl, g_wt[2][0], g_wt[2][1], tid);
    mma_span(acc, sm + O_XH, sm + O_WA, sm + O_WB, 0, 8, warp, g, tig);
    __syncthreads();
    pf_store(sm + O_WA, sm + O_WB, pfh, pfl, tid);
    __syncthreads();

    // phase B: agg @ W1b  (prefetch W2 during span)
    pf_load(pfh, pfl, g_wt[3][0], g_wt[3][1], tid);
    mma_span(acc, sm + O_TH, sm + O_WA, sm + O_WB, 0, 8, warp, g, tig);
    __syncthreads();
    pf_store(sm + O_WA, sm + O_WB, pfh, pfl, tid);

    // h1 = silu(acc + b1) -> fp16 back into T tile
    {
        const float* b1s = (const float*)(sm + O_B1);
        int r_hi = warp * 16 + g;
#pragma unroll
        for (int nt = 0; nt < 16; nt++) {
            int c0 = nt * 8 + tig * 2;
            float bb0 = b1s[c0], bb1 = b1s[c0 + 1];
#pragma unroll
            for (int half = 0; half < 2; half++) {
                int r = r_hi + half * 8;
                float z0 = acc[nt * 4 + half * 2 + 0] + bb0;
                float z1 = acc[nt * 4 + half * 2 + 1] + bb1;
                float v0 = z0 * lut_sigma_g(z0);
                float v1 = z1 * lut_sigma_g(z1);
                __half h0 = __float2half_rn(v0);
                __half h1 = __float2half_rn(v1);
                unsigned int hp = ((unsigned int)__half_as_ushort(h1) << 16)
                                | __half_as_ushort(h0);
                int off = (r * TSTRIDE + c0) * 2;
                *(unsigned int*)(sm + O_TH + off) = hp;
            }
        }
    }
    __syncthreads();

    // phase C: h1 @ W2   (prefetch resW during span)
#pragma unroll
    for (int i = 0; i < 64; i++) acc[i] = 0.f;
    pf_load(pfh, pfl, g_wt[4][0], g_wt[4][1], tid);
    mma_span(acc, sm + O_TH, sm + O_WA, sm + O_WB, 0, 8, warp, g, tig);
    __syncthreads();
    pf_store(sm + O_WA, sm + O_WB, pfh, pfl, tid);
    __syncthreads();

    // phase D: x @ resW
    mma_span(acc, sm + O_XH, sm + O_WA, sm + O_WB, 0, 8, warp, g, tig);

    // epilogue: z = acc + b2, per-row LayerNorm via quad reduction
    {
        const float* b2s = (const float*)(sm + O_B2);
        const float* lg  = (const float*)(sm + O_LG);
        const float* lb  = (const float*)(sm + O_LB);

        float sA = 0.f, qA = 0.f, sB = 0.f, qB = 0.f;
#pragma unroll
        for (int nt = 0; nt < 16; nt++) {
            int c0 = nt * 8 + tig * 2;
            float bb0 = b2s[c0], bb1 = b2s[c0 + 1];
            float z0 = acc[nt * 4 + 0] + bb0, z1 = acc[nt * 4 + 1] + bb1;
            float z2 = acc[nt * 4 + 2] + bb0, z3 = acc[nt * 4 + 3] + bb1;
            acc[nt * 4 + 0] = z0; acc[nt * 4 + 1] = z1;
            acc[nt * 4 + 2] = z2; acc[nt * 4 + 3] = z3;
            sA += z0 + z1; qA += z0 * z0 + z1 * z1;
            sB += z2 + z3; qB += z2 * z2 + z3 * z3;
        }
#pragma unroll
        for (int m = 1; m <= 2; m <<= 1) {
            sA += __shfl_xor_sync(0xffffffffu, sA, m);
            qA += __shfl_xor_sync(0xffffffffu, qA, m);
            sB += __shfl_xor_sync(0xffffffffu, sB, m);
            qB += __shfl_xor_sync(0xffffffffu, qB, m);
        }
        float muA = sA * (1.f / 128.f);
        float rsA = rsqrtf(qA * (1.f / 128.f) - muA * muA + LNEPS);
        float muB = sB * (1.f / 128.f);
        float rsB = rsqrtf(qB * (1.f / 128.f) - muB * muB + LNEPS);

        int r_hi = row0 + warp * 16 + g;
        int r_lo = r_hi + 8;
#pragma unroll
        for (int nt = 0; nt < 16; nt++) {
            int c0 = nt * 8 + tig * 2;
            float g0 = lg[c0], g1 = lg[c0 + 1];
            float o0 = lb[c0], o1 = lb[c0 + 1];
            if (r_hi < n) {
                float2 v;
                v.x = (acc[nt * 4 + 0] - muA) * rsA * g0 + o0;
                v.y = (acc[nt * 4 + 1] - muA) * rsA * g1 + o1;
                *(float2*)(out + r_hi * DD + c0) = v;
            }
            if (r_lo < n) {
                float2 v;
                v.x = (acc[nt * 4 + 2] - muB) * rsB * g0 + o0;
                v.y = (acc[nt * 4 + 3] - muB) * rsB * g1 + o1;
                *(float2*)(out + r_lo * DD + c0) = v;
            }
        }
    }
}

// ---------------- launch -----------------------------------------------------------
extern "C" void kernel_launch(void* const* d_in, const int* in_sizes, int n_in,
                              void* d_out, int out_size) {
    const float* x    = (const float*)d_in[0];
    const int*   ei   = (const int*)  d_in[1];
    const float* ea   = (const float*)d_in[2];
    const float* aggW = (const float*)d_in[3];
    const float* aggb = (const float*)d_in[4];
    const float* eW1  = (const float*)d_in[5];
    const float* eb1  = (const float*)d_in[6];
    const float* eW2  = (const float*)d_in[7];
    const float* eb2  = (const float*)d_in[8];
    const float* uW1  = (const float*)d_in[9];
    const float* ub1  = (const float*)d_in[10];
    const float* uW2  = (const float*)d_in[11];
    const float* ub2  = (const float*)d_in[12];
    const float* lng  = (const float*)d_in[13];
    const float* lnb  = (const float*)d_in[14];
    const float* resW = (const float*)d_in[15];

    int n = in_sizes[0] / DD;
    int E = in_sizes[2] / 4;

    const int SMEM_A = 512 + 3 * TBYTES;    // 104960 -> 2 blocks/SM
    const int SMEM_U = 2048 + 4 * TBYTES;   // 141312
    cudaFuncSetAttribute(k_agg_m,   cudaFuncAttributeMaxDynamicSharedMemorySize, SMEM_A);
    cudaFuncSetAttribute(k_upd12_m, cudaFuncAttributeMaxDynamicSharedMemorySize, SMEM_U);

    // edge-MLP weights -> constant memory (D2D memcpy nodes, graph-capturable)
    cudaMemcpyToSymbolAsync(c_w1s, eW1, 4 * DD * sizeof(float), 0, cudaMemcpyDeviceToDevice);
    cudaMemcpyToSymbolAsync(c_b1s, eb1, DD * sizeof(float), 0, cudaMemcpyDeviceToDevice);
    cudaMemcpyToSymbolAsync(c_w2s, eW2, DD * sizeof(float), 0, cudaMemcpyDeviceToDevice);

    int gblocks = (n + 127) / 128;   // 782

    // 4th kernel launch (k_gate) is the profiled one this round
    k_lut_zcnt<<<512, 256>>>(n);                                        // 1
    k_count_wprep<<<1024, 256>>>(ei, E, aggW, uW1, uW2, resW);          // 2
    k_scan_fused<<<1, 1024>>>(n, E);                                    // 3
    k_gate<<<888, 256>>>(ei, ea, eb2, E);                               // 4 <- profiled
    k_agg_m<<<gblocks, 256, SMEM_A>>>(x, aggb, n);                      // 5
    k_gather<<<2048, 256>>>(n);                                         // 6
    k_upd12_m<<<gblocks, 256, SMEM_U>>>(x, ub1, ub2, lng, lnb,
                                        (float*)d_out, n);              // 7
}

// round 15
// speedup vs baseline: 1.1889x; 1.1889x over previous
#include <cuda_runtime.h>
#include <cuda_fp16.h>
#include <cstdint>
#include <math.h>

#define DD 128
#define NMAX 100000
#define EMAX 1600000
#define LUTN 2048
#define NNL 8192
#define LNEPS 1e-5f
#define TSTRIDE 136                    // fp16 elems per smem tile row (bank-safe)
#define TBYTES (128 * TSTRIDE * 2)     // 34816 B per 128x128 fp16 tile
#define TU4 (TBYTES / 16)

typedef unsigned long long ull;

// ---------------- scratch (static device globals) ---------------------------
__device__ __half g_ax[NMAX * DD];     // silu(x @ agg_W + b), fp16
__device__ int    g_cnti[NMAX];
__device__ int    g_rows[NMAX + 1];
__device__ int    g_cur[NMAX];
__device__ int    g_csr_src[EMAX];
__device__ float  g_csr_w[EMAX];
__device__ float2 g_lut[LUTN + 1];     // interp sigmoid {s_i - i*d_i, d_i}
__device__ float  g_nn[NNL];           // NN sigmoid table (gate)
// pre-split transposed fp16 weights, [N rows][K cols] stride TSTRIDE:
// mats: 0=aggW, 1=uW1[:128], 2=uW1[128:], 3=uW2, 4=resW
__device__ __align__(16) unsigned char g_wt[5][2][TBYTES];

// ---------------- packed f32x2 helpers (gate kernel) --------------------------
__device__ __forceinline__ ull pack_dup(float a) {
    unsigned int au = __float_as_uint(a);
    ull r; asm("mov.b64 %0, {%1, %1};" : "=l"(r) : "r"(au)); return r;
}
__device__ __forceinline__ ull pack2(float lo, float hi) {
    ull r; asm("mov.b64 %0, {%1, %2};" : "=l"(r) : "r"(__float_as_uint(lo)), "r"(__float_as_uint(hi))); return r;
}
__device__ __forceinline__ void fma2(ull& d, ull a, ull b) {
    asm("fma.rn.f32x2 %0, %1, %2, %0;" : "+l"(d) : "l"(a), "l"(b));
}
__device__ __forceinline__ ull mul2(ull a, ull b) {
    ull r; asm("mul.rn.f32x2 %0, %1, %2;" : "=l"(r) : "l"(a), "l"(b)); return r;
}
__device__ __forceinline__ void unpack2(ull v, float& lo, float& hi) {
    unsigned int l, h;
    asm("mov.b64 {%0, %1}, %2;" : "=r"(l), "=r"(h) : "l"(v));
    lo = __uint_as_float(l); hi = __uint_as_float(h);
}

// ---------------- sigmoid LUT --------------------------------------------------
__device__ __forceinline__ float lut_sigma_g(float z) {
    float t = fminf(fmaxf(fmaf(z, 128.f, 1024.f), 0.f), 2047.99f);
    float2 e = __ldg(&g_lut[(int)t]);
    return fmaf(e.y, t, e.x);
}

// ---------------- fp16 mma.sync (sm_70+ baseline) ------------------------------
#define MMA4(c, a, b0, b1) \
    asm volatile("mma.sync.aligned.m16n8k16.row.col.f32.f16.f16.f32 " \
        "{%0,%1,%2,%3}, {%4,%5,%6,%7}, {%8,%9}, {%0,%1,%2,%3};" \
        : "+f"((c)[0]), "+f"((c)[1]), "+f"((c)[2]), "+f"((c)[3]) \
        : "r"((a)[0]), "r"((a)[1]), "r"((a)[2]), "r"((a)[3]), "r"(b0), "r"(b1))

// s-outer / nt-inner GEMM span, 2-term (A fp16, W split hi+lo fp16)
__device__ __forceinline__ void mma_span(float* acc,
    const char* Ah, const char* Wh, const char* Wl,
    int s0, int s1, int warp, int g, int tig) {
    const char* arow = Ah + ((warp * 16 + g) * TSTRIDE + tig * 2) * 2;
#pragma unroll
    for (int s = s0; s < s1; s++) {
        unsigned int afH[4];
        const char* pa = arow + s * 32;
        afH[0] = *(const unsigned int*)(pa);
        afH[1] = *(const unsigned int*)(pa + 8 * TSTRIDE * 2);
        afH[2] = *(const unsigned int*)(pa + 16);
        afH[3] = *(const unsigned int*)(pa + 8 * TSTRIDE * 2 + 16);
        int kb = s * 32;
#pragma unroll
        for (int nt = 0; nt < 16; nt++) {
            const char* bh = Wh + (nt * 8 + g) * (TSTRIDE * 2) + tig * 4 + kb;
            const char* bl = Wl + (nt * 8 + g) * (TSTRIDE * 2) + tig * 4 + kb;
            unsigned int b0h = *(const unsigned int*)(bh);
            unsigned int b1h = *(const unsigned int*)(bh + 16);
            unsigned int b0l = *(const unsigned int*)(bl);
            unsigned int b1l = *(const unsigned int*)(bl + 16);
            float* c = acc + nt * 4;
            MMA4(c, afH, b0h, b1h);
            MMA4(c, afH, b0l, b1l);
        }
    }
}

// fp32 [128 rows] tile -> fp16 smem tile (256 threads)
__device__ __forceinline__ void conv_tileH(char* hi, const float* __restrict__ src,
                                           int row0, int n, int tid) {
#pragma unroll
    for (int i = 0; i < 8; i++) {
        int ch = tid + 256 * i;
        int row = ch >> 4, part = ch & 15;
        int gr = row0 + row;
        float4 v0 = make_float4(0.f, 0.f, 0.f, 0.f);
        float4 v1 = make_float4(0.f, 0.f, 0.f, 0.f);
        if (gr < n) {
            const float4* p = (const float4*)(src + gr * DD + part * 8);
            v0 = __ldg(p);
            v1 = __ldg(p + 1);
        }
        float s[8];
        s[0] = v0.x; s[1] = v0.y; s[2] = v0.z; s[3] = v0.w;
        s[4] = v1.x; s[5] = v1.y; s[6] = v1.z; s[7] = v1.w;
        union { uint4 u; __half h[8]; } H;
#pragma unroll
        for (int j = 0; j < 8; j++) H.h[j] = __float2half_rn(s[j]);
        int off = (row * TSTRIDE + part * 8) * 2;
        *(uint4*)(hi + off) = H.u;
    }
}

// full weight tile pair global -> smem (256 threads)
__device__ __forceinline__ void load_wt256(char* hi, char* lo,
                                           const unsigned char* gh,
                                           const unsigned char* gl, int tid) {
#pragma unroll
    for (int i = 0; i < 9; i++) {
        int idx = tid + 256 * i;
        if (idx < TU4) {
            ((uint4*)hi)[idx] = __ldg((const uint4*)gh + idx);
            ((uint4*)lo)[idx] = __ldg((const uint4*)gl + idx);
        }
    }
}

// ---------------- LUT build + count zero ---------------------------------------
__global__ void k_lut_zcnt(int n) {
    int stride = blockDim.x * gridDim.x;
    for (int i = threadIdx.x + blockIdx.x * blockDim.x; i <= LUTN; i += stride) {
        float z0 = -8.f + (float)i * (16.f / LUTN);
        float z1 = z0 + (16.f / LUTN);
        float s0 = 1.f / (1.f + expf(-z0));
        float s1 = 1.f / (1.f + expf(-z1));
        float d  = s1 - s0;
        g_lut[i] = make_float2(s0 - (float)i * d, d);
    }
    for (int i = threadIdx.x + blockIdx.x * blockDim.x; i < NNL; i += stride) {
        float z = -8.f + ((float)i + 0.5f) * (16.f / NNL);
        g_nn[i] = 1.f / (1.f + expf(-z));
    }
    for (int i = threadIdx.x + blockIdx.x * blockDim.x; i < n; i += stride)
        g_cnti[i] = 0;
}

// ---------------- fused: degree count + weight prep -----------------------------
__global__ void k_count_wprep(const int* __restrict__ ei, int E,
                              const float* __restrict__ aggW, const float* __restrict__ uW1,
                              const float* __restrict__ uW2, const float* __restrict__ resW) {
    int tid0 = threadIdx.x + blockIdx.x * blockDim.x;
    int stride = blockDim.x * gridDim.x;
    for (int idx = tid0; idx < 5 * 16384; idx += stride) {
        int mat = idx >> 14, e = idx & 16383;
        int k = e >> 7, col = e & 127;
        const float* src = (mat == 0) ? aggW : (mat == 1) ? uW1 : (mat == 2) ? (uW1 + 16384)
                         : (mat == 3) ? uW2 : resW;
        float v = __ldg(&src[k * DD + col]);
        __half h = __float2half_rn(v);
        __half l = __float2half_rn(v - __half2float(h));
        int off = (col * TSTRIDE + k) * 2;
        *(__half*)(&g_wt[mat][0][off]) = h;
        *(__half*)(&g_wt[mat][1][off]) = l;
    }
    for (int i = tid0; i < E; i += stride)
        atomicAdd(&g_cnti[__ldg(&ei[E + i])], 1);
}

__global__ void __launch_bounds__(1024)
k_scan_fused(int n, int E) {
    __shared__ int sh[1024];
    int t = threadIdx.x;
    int len = (n + 1023) / 1024;
    int s = t * len;
    int e = min(s + len, n);
    int sum = 0;
    for (int i = s; i < e; i++) sum += g_cnti[i];
    sh[t] = sum;
    __syncthreads();
    for (int o = 1; o < 1024; o <<= 1) {
        int u = (t >= o) ? sh[t - o] : 0;
        __syncthreads();
        sh[t] += u;
        __syncthreads();
    }
    int excl = sh[t] - sum;
    for (int i = s; i < e; i++) {
        int c = g_cnti[i];
        g_rows[i] = excl;
        g_cur[i]  = excl;
        excl += c;
    }
    if (t == 0) g_rows[n] = E;
}

// ---------------- edge gate + CSR permute (thread per edge, smem weights) --------
__global__ void __launch_bounds__(256)
k_gate(const int* __restrict__ ei, const float* __restrict__ ea,
       const float* __restrict__ W1, const float* __restrict__ b1,
       const float* __restrict__ W2, const float* __restrict__ b2p, int E) {
    __shared__ float nn[NNL];
    __shared__ ull w1s[4][64];
    __shared__ ull b1s[64];
    __shared__ ull w2s[64];

    for (int i = threadIdx.x; i < NNL; i += blockDim.x) nn[i] = g_nn[i];
    if (threadIdx.x < 64) {
        int c2 = threadIdx.x;
#pragma unroll
        for (int k = 0; k < 4; k++)
            w1s[k][c2] = __ldg((const ull*)(W1 + k * DD) + c2);
        b1s[c2] = __ldg((const ull*)b1 + c2);
        w2s[c2] = __ldg((const ull*)W2 + c2);
    }
    __syncthreads();

    float b2v = __ldg(b2p);
    int stride = blockDim.x * gridDim.x;
    int e0 = threadIdx.x + blockIdx.x * blockDim.x;

    int src = 0, dst = 0;
    float4 a = make_float4(0.f, 0.f, 0.f, 0.f);
    if (e0 < E) {
        src = __ldg(&ei[e0]);
        dst = __ldg(&ei[E + e0]);
        a   = __ldg((const float4*)(ea + 4 * e0));
    }

    for (int e = e0; e < E; ) {
        int srcC = src, dstC = dst;
        float4 aC = a;
        int eN = e + stride;
        if (eN < E) {
            src = __ldg(&ei[eN]);
            dst = __ldg(&ei[E + eN]);
            a   = __ldg((const float4*)(ea + 4 * eN));
        }

        ull ax = pack_dup(aC.x), ay = pack_dup(aC.y);
        ull az = pack_dup(aC.z), aw = pack_dup(aC.w);
        ull dot2 = 0ull;
#pragma unroll 16
        for (int c2 = 0; c2 < 64; c2++) {
            ull zz = b1s[c2];
            fma2(zz, ax, w1s[0][c2]);
            fma2(zz, ay, w1s[1][c2]);
            fma2(zz, az, w1s[2][c2]);
            fma2(zz, aw, w1s[3][c2]);
            float z0, z1;
            unpack2(zz, z0, z1);
            float t0 = fminf(fmaxf(fmaf(z0, 512.f, 4096.f), 0.f), 8191.f);
            float t1 = fminf(fmaxf(fmaf(z1, 512.f, 4096.f), 0.f), 8191.f);
            ull zs = mul2(zz, pack2(nn[(int)t0], nn[(int)t1]));
            fma2(dot2, zs, w2s[c2]);
        }
        float d0, d1;
        unpack2(dot2, d0, d1);
        float zg = d0 + d1 + b2v;
        float tg = fminf(fmaxf(fmaf(zg, 512.f, 4096.f), 0.f), 8191.f);
        float ew = nn[(int)tg];

        int pos = atomicAdd(&g_cur[dstC], 1);
        g_csr_src[pos] = srcC;
        g_csr_w[pos]   = ew;
        e = eN;
    }
}

// ---------------- K1 (HMMA fp16): g_ax = silu(x @ agg_W + b) ---------------------
// smem: bias 512 + AH + WH + WL = 512 + 3*34816 = 104960 -> 2 blocks/SM
__global__ void __launch_bounds__(256, 2)
k_agg_m(const float* __restrict__ x, const float* __restrict__ bias, int n) {
    extern __shared__ char sm[];
    const int O_B = 0, O_AH = 512, O_WH = O_AH + TBYTES, O_WL = O_WH + TBYTES;
    int tid = threadIdx.x;
    int row0 = blockIdx.x * 128;

    if (tid < 128) ((float*)(sm + O_B))[tid] = __ldg(&bias[tid]);
    conv_tileH(sm + O_AH, x, row0, n, tid);
    load_wt256(sm + O_WH, sm + O_WL, g_wt[0][0], g_wt[0][1], tid);
    __syncthreads();

    int lane = tid & 31, warp = tid >> 5;
    int g = lane >> 2, tig = lane & 3;

    float acc[64];
#pragma unroll
    for (int i = 0; i < 64; i++) acc[i] = 0.f;
    mma_span(acc, sm + O_AH, sm + O_WH, sm + O_WL, 0, 8, warp, g, tig);

    const float* bs = (const float*)(sm + O_B);
    int r_hi = row0 + warp * 16 + g;
    int r_lo = r_hi + 8;
#pragma unroll
    for (int nt = 0; nt < 16; nt++) {
        int c0 = nt * 8 + tig * 2;
        float b0 = bs[c0], b1v = bs[c0 + 1];
        if (r_hi < n) {
            float z0 = acc[nt * 4 + 0] + b0, z1 = acc[nt * 4 + 1] + b1v;
            __half2 v = __floats2half2_rn(z0 * lut_sigma_g(z0), z1 * lut_sigma_g(z1));
            *(__half2*)(g_ax + r_hi * DD + c0) = v;
        }
        if (r_lo < n) {
            float z0 = acc[nt * 4 + 2] + b0, z1 = acc[nt * 4 + 3] + b1v;
            __half2 v = __floats2half2_rn(z0 * lut_sigma_g(z0), z1 * lut_sigma_g(z1));
            *(__half2*)(g_ax + r_lo * DD + c0) = v;
        }
    }
}

// ---------------- fused update: gather + 4 GEMMs + LN ----------------------------
// smem: params 2048 + XH, TH, WH, WL = 2048 + 4*34816 = 141312
__device__ __forceinline__ void acc_half4(float4& a, unsigned int lo, unsigned int hi, float w) {
    float2 f0 = __half22float2(*(__half2*)&lo);
    float2 f1 = __half22float2(*(__half2*)&hi);
    a.x = fmaf(w, f0.x, a.x); a.y = fmaf(w, f0.y, a.y);
    a.z = fmaf(w, f1.x, a.z); a.w = fmaf(w, f1.y, a.w);
}

__global__ void __launch_bounds__(256)
k_upd12_m(const float* __restrict__ x,
          const float* __restrict__ b1, const float* __restrict__ b2,
          const float* __restrict__ lng, const float* __restrict__ lnb,
          float* __restrict__ out, int n) {
    extern __shared__ char sm[];
    const int O_B1 = 0, O_B2 = 512, O_LG = 1024, O_LB = 1536,
              O_XH = 2048, O_TH = O_XH + TBYTES,
              O_WH = O_TH + TBYTES, O_WL = O_WH + TBYTES;
    int tid = threadIdx.x;
    int lane = tid & 31, warp = tid >> 5;
    int row0 = blockIdx.x * 128;

    if (tid < 128) {
        ((float*)(sm + O_B1))[tid] = __ldg(&b1[tid]);
        ((float*)(sm + O_B2))[tid] = __ldg(&b2[tid]);
        ((float*)(sm + O_LG))[tid] = __ldg(&lng[tid]);
        ((float*)(sm + O_LB))[tid] = __ldg(&lnb[tid]);
    }

    // fused gather: warp w aggregates nodes row0 + w*16 .. +15 directly into TH
    for (int k = 0; k < 16; k++) {
        int r = warp * 16 + k;
        int i = row0 + r;
        float4 a0 = make_float4(0.f, 0.f, 0.f, 0.f);
        float4 a1 = make_float4(0.f, 0.f, 0.f, 0.f);
        float4 a2 = make_float4(0.f, 0.f, 0.f, 0.f);
        float4 a3 = make_float4(0.f, 0.f, 0.f, 0.f);
        float rv = 0.f;
        if (i < n) {
            int s = g_rows[i], e = g_rows[i + 1];
            int j = s;
            for (; j + 3 < e; j += 4) {
                int   s0 = __ldg(&g_csr_src[j]);
                int   s1 = __ldg(&g_csr_src[j + 1]);
                int   s2 = __ldg(&g_csr_src[j + 2]);
                int   s3 = __ldg(&g_csr_src[j + 3]);
                float w0 = __ldg(&g_csr_w[j]);
                float w1 = __ldg(&g_csr_w[j + 1]);
                float w2 = __ldg(&g_csr_w[j + 2]);
                float w3 = __ldg(&g_csr_w[j + 3]);
                uint2 v0 = __ldg((const uint2*)(g_ax + s0 * DD + lane * 4));
                uint2 v1 = __ldg((const uint2*)(g_ax + s1 * DD + lane * 4));
                uint2 v2 = __ldg((const uint2*)(g_ax + s2 * DD + lane * 4));
                uint2 v3 = __ldg((const uint2*)(g_ax + s3 * DD + lane * 4));
                acc_half4(a0, v0.x, v0.y, w0);
                acc_half4(a1, v1.x, v1.y, w1);
                acc_half4(a2, v2.x, v2.y, w2);
                acc_half4(a3, v3.x, v3.y, w3);
            }
            for (; j < e; j++) {
                int   s0 = __ldg(&g_csr_src[j]);
                float w0 = __ldg(&g_csr_w[j]);
                uint2 v0 = __ldg((const uint2*)(g_ax + s0 * DD + lane * 4));
                acc_half4(a0, v0.x, v0.y, w0);
            }
            rv = 1.f / fmaxf((float)(e - s), 1.f);
        }
        float ox = (a0.x + a1.x + a2.x + a3.x) * rv;
        float oy = (a0.y + a1.y + a2.y + a3.y) * rv;
        float oz = (a0.z + a1.z + a2.z + a3.z) * rv;
        float ow = (a0.w + a1.w + a2.w + a3.w) * rv;
        union { uint2 u; __half h[4]; } O;
        O.h[0] = __float2half_rn(ox); O.h[1] = __float2half_rn(oy);
        O.h[2] = __float2half_rn(oz); O.h[3] = __float2half_rn(ow);
        *(uint2*)(sm + O_TH + (r * TSTRIDE + lane * 4) * 2) = O.u;
    }

    conv_tileH(sm + O_XH, x, row0, n, tid);
    load_wt256(sm + O_WH, sm + O_WL, g_wt[1][0], g_wt[1][1], tid);
    __syncthreads();

    int g = lane >> 2, tig = lane & 3;

    float acc[64];
#pragma unroll
    for (int i = 0; i < 64; i++) acc[i] = 0.f;

    // phase A: x @ W1a
    mma_span(acc, sm + O_XH, sm + O_WH, sm + O_WL, 0, 8, warp, g, tig);
    __syncthreads();

    // phase B: agg @ W1b
    load_wt256(sm + O_WH, sm + O_WL, g_wt[2][0], g_wt[2][1], tid);
    __syncthreads();
    mma_span(acc, sm + O_TH, sm + O_WH, sm + O_WL, 0, 8, warp, g, tig);
    __syncthreads();

    // h1 = silu(acc + b1) -> fp16 back into T tile; load W2
    {
        const float* b1s = (const float*)(sm + O_B1);
        int r_hi = warp * 16 + g;
#pragma unroll
        for (int nt = 0; nt < 16; nt++) {
            int c0 = nt * 8 + tig * 2;
            float bb0 = b1s[c0], bb1 = b1s[c0 + 1];
#pragma unroll
            for (int half = 0; half < 2; half++) {
                int r = r_hi + half * 8;
                float z0 = acc[nt * 4 + half * 2 + 0] + bb0;
                float z1 = acc[nt * 4 + half * 2 + 1] + bb1;
                float v0 = z0 * lut_sigma_g(z0);
                float v1 = z1 * lut_sigma_g(z1);
                __half h0 = __float2half_rn(v0);
                __half h1 = __float2half_rn(v1);
                unsigned int hp = ((unsigned int)__half_as_ushort(h1) << 16)
                                | __half_as_ushort(h0);
                int off = (r * TSTRIDE + c0) * 2;
                *(unsigned int*)(sm + O_TH + off) = hp;
            }
        }
        load_wt256(sm + O_WH, sm + O_WL, g_wt[3][0], g_wt[3][1], tid);
    }
    __syncthreads();

    // phase C: h1 @ W2
#pragma unroll
    for (int i = 0; i < 64; i++) acc[i] = 0.f;
    mma_span(acc, sm + O_TH, sm + O_WH, sm + O_WL, 0, 8, warp, g, tig);
    __syncthreads();

    // phase D: x @ resW
    load_wt256(sm + O_WH, sm + O_WL, g_wt[4][0], g_wt[4][1], tid);
    __syncthreads();
    mma_span(acc, sm + O_XH, sm + O_WH, sm + O_WL, 0, 8, warp, g, tig);

    // epilogue: z = acc + b2, per-row LayerNorm via quad reduction
    {
        const float* b2s = (const float*)(sm + O_B2);
        const float* lg  = (const float*)(sm + O_LG);
        const float* lb  = (const float*)(sm + O_LB);

        float sA = 0.f, qA = 0.f, sB = 0.f, qB = 0.f;
#pragma unroll
        for (int nt = 0; nt < 16; nt++) {
            int c0 = nt * 8 + tig * 2;
            float bb0 = b2s[c0], bb1 = b2s[c0 + 1];
            float z0 = acc[nt * 4 + 0] + bb0, z1 = acc[nt * 4 + 1] + bb1;
            float z2 = acc[nt * 4 + 2] + bb0, z3 = acc[nt * 4 + 3] + bb1;
            acc[nt * 4 + 0] = z0; acc[nt * 4 + 1] = z1;
            acc[nt * 4 + 2] = z2; acc[nt * 4 + 3] = z3;
            sA += z0 + z1; qA += z0 * z0 + z1 * z1;
            sB += z2 + z3; qB += z2 * z2 + z3 * z3;
        }
#pragma unroll
        for (int m = 1; m <= 2; m <<= 1) {
            sA += __shfl_xor_sync(0xffffffffu, sA, m);
            qA += __shfl_xor_sync(0xffffffffu, qA, m);
            sB += __shfl_xor_sync(0xffffffffu, sB, m);
            qB += __shfl_xor_sync(0xffffffffu, qB, m);
        }
        float muA = sA * (1.f / 128.f);
        float rsA = rsqrtf(qA * (1.f / 128.f) - muA * muA + LNEPS);
        float muB = sB * (1.f / 128.f);
        float rsB = rsqrtf(qB * (1.f / 128.f) - muB * muB + LNEPS);

        int r_hi = row0 + warp * 16 + g;
        int r_lo = r_hi + 8;
#pragma unroll
        for (int nt = 0; nt < 16; nt++) {
            int c0 = nt * 8 + tig * 2;
            float g0 = lg[c0], g1 = lg[c0 + 1];
            float o0 = lb[c0], o1 = lb[c0 + 1];
            if (r_hi < n) {
                float2 v;
                v.x = (acc[nt * 4 + 0] - muA) * rsA * g0 + o0;
                v.y = (acc[nt * 4 + 1] - muA) * rsA * g1 + o1;
                *(float2*)(out + r_hi * DD + c0) = v;
            }
            if (r_lo < n) {
                float2 v;
                v.x = (acc[nt * 4 + 2] - muB) * rsB * g0 + o0;
                v.y = (acc[nt * 4 + 3] - muB) * rsB * g1 + o1;
                *(float2*)(out + r_lo * DD + c0) = v;
            }
        }
    }
}

// ---------------- launch -----------------------------------------------------------
extern "C" void kernel_launch(void* const* d_in, const int* in_sizes, int n_in,
                              void* d_out, int out_size) {
    const float* x    = (const float*)d_in[0];
    const int*   ei   = (const int*)  d_in[1];
    const float* ea   = (const float*)d_in[2];
    const float* aggW = (const float*)d_in[3];
    const float* aggb = (const float*)d_in[4];
    const float* eW1  = (const float*)d_in[5];
    const float* eb1  = (const float*)d_in[6];
    const float* eW2  = (const float*)d_in[7];
    const float* eb2  = (const float*)d_in[8];
    const float* uW1  = (const float*)d_in[9];
    const float* ub1  = (const float*)d_in[10];
    const float* uW2  = (const float*)d_in[11];
    const float* ub2  = (const float*)d_in[12];
    const float* lng  = (const float*)d_in[13];
    const float* lnb  = (const float*)d_in[14];
    const float* resW = (const float*)d_in[15];

    int n = in_sizes[0] / DD;
    int E = in_sizes[2] / 4;

    const int SMEM_A = 512 + 3 * TBYTES;    // 104960 -> 2 blocks/SM
    const int SMEM_U = 2048 + 4 * TBYTES;   // 141312
    cudaFuncSetAttribute(k_agg_m,   cudaFuncAttributeMaxDynamicSharedMemorySize, SMEM_A);
    cudaFuncSetAttribute(k_upd12_m, cudaFuncAttributeMaxDynamicSharedMemorySize, SMEM_U);

    int gblocks = (n + 127) / 128;   // 782

    // 4th launch (k_gate) is the profiled one -> verify revert restores ~158us
    k_lut_zcnt<<<512, 256>>>(n);                                        // 1
    k_count_wprep<<<1024, 256>>>(ei, E, aggW, uW1, uW2, resW);          // 2
    k_scan_fused<<<1, 1024>>>(n, E);                                    // 3
    k_gate<<<888, 256>>>(ei, ea, eW1, eb1, eW2, eb2, E);                // 4 <- profiled
    k_agg_m<<<gblocks, 256, SMEM_A>>>(x, aggb, n);                      // 5
    k_upd12_m<<<gblocks, 256, SMEM_U>>>(x, ub1, ub2, lng, lnb,
                                        (float*)d_out, n);              // 6
}

// round 16
// speedup vs baseline: 1.6875x; 1.4193x over previous
#include <cuda_runtime.h>
#include <cuda_fp16.h>
#include <cstdint>
#include <math.h>

#define DD 128
#define NMAX 100000
#define EMAX 1600000
#define LUTN 2048
#define LNEPS 1e-5f
#define TSTRIDE 136                    // fp16 elems per smem tile row (bank-safe)
#define TBYTES (128 * TSTRIDE * 2)     // 34816 B per 128x128 fp16 tile
#define TU4 (TBYTES / 16)

typedef unsigned long long ull;

// ---------------- scratch (static device globals) ---------------------------
__device__ __half g_ax[NMAX * DD];     // silu(x @ agg_W + b), fp16
__device__ __half g_agg[NMAX * DD];    // mean-aggregated messages, fp16
__device__ int    g_cnti[NMAX];
__device__ int    g_rows[NMAX + 1];
__device__ int    g_cur[NMAX];
__device__ int    g_csr_src[EMAX];
__device__ float  g_csr_w[EMAX];
__device__ float2 g_lut[LUTN + 1];     // interp sigmoid {s_i - i*d_i, d_i} (GEMM epilogues)
// pre-split transposed fp16 weights, [N rows][K cols] stride TSTRIDE:
// mats: 0=aggW, 1=uW1[:128], 2=uW1[128:], 3=uW2, 4=resW
__device__ __align__(16) unsigned char g_wt[5][2][TBYTES];

// ---------------- packed f32x2 helpers (gate kernel) --------------------------
__device__ __forceinline__ ull pack_dup(float a) {
    unsigned int au = __float_as_uint(a);
    ull r; asm("mov.b64 %0, {%1, %1};" : "=l"(r) : "r"(au)); return r;
}
__device__ __forceinline__ ull pack2(float lo, float hi) {
    ull r; asm("mov.b64 %0, {%1, %2};" : "=l"(r) : "r"(__float_as_uint(lo)), "r"(__float_as_uint(hi))); return r;
}
__device__ __forceinline__ void fma2(ull& d, ull a, ull b) {
    asm("fma.rn.f32x2 %0, %1, %2, %0;" : "+l"(d) : "l"(a), "l"(b));
}
__device__ __forceinline__ void unpack2(ull v, float& lo, float& hi) {
    unsigned int l, h;
    asm("mov.b64 {%0, %1}, %2;" : "=r"(l), "=r"(h) : "l"(v));
    lo = __uint_as_float(l); hi = __uint_as_float(h);
}
__device__ __forceinline__ float tanhap(float x) {
    float r;
    asm("tanh.approx.f32 %0, %1;" : "=f"(r) : "f"(x));
    return r;
}
// sigmoid via 1 MUFU: 0.5 + 0.5*tanh(z/2)
__device__ __forceinline__ float sig_t(float z) {
    return fmaf(tanhap(z * 0.5f), 0.5f, 0.5f);
}

// ---------------- sigmoid LUT (GEMM epilogues) ----------------------------------
__device__ __forceinline__ float lut_sigma_g(float z) {
    float t = fminf(fmaxf(fmaf(z, 128.f, 1024.f), 0.f), 2047.99f);
    float2 e = __ldg(&g_lut[(int)t]);
    return fmaf(e.y, t, e.x);
}

// ---------------- fp16 mma.sync (sm_70+ baseline) ------------------------------
#define MMA4(c, a, b0, b1) \
    asm volatile("mma.sync.aligned.m16n8k16.row.col.f32.f16.f16.f32 " \
        "{%0,%1,%2,%3}, {%4,%5,%6,%7}, {%8,%9}, {%0,%1,%2,%3};" \
        : "+f"((c)[0]), "+f"((c)[1]), "+f"((c)[2]), "+f"((c)[3]) \
        : "r"((a)[0]), "r"((a)[1]), "r"((a)[2]), "r"((a)[3]), "r"(b0), "r"(b1))

// s-outer / nt-inner GEMM span, 2-term (A fp16, W split hi+lo fp16)
__device__ __forceinline__ void mma_span(float* acc,
    const char* Ah, const char* Wh, const char* Wl,
    int s0, int s1, int warp, int g, int tig) {
    const char* arow = Ah + ((warp * 16 + g) * TSTRIDE + tig * 2) * 2;
#pragma unroll
    for (int s = s0; s < s1; s++) {
        unsigned int afH[4];
        const char* pa = arow + s * 32;
        afH[0] = *(const unsigned int*)(pa);
        afH[1] = *(const unsigned int*)(pa + 8 * TSTRIDE * 2);
        afH[2] = *(const unsigned int*)(pa + 16);
        afH[3] = *(const unsigned int*)(pa + 8 * TSTRIDE * 2 + 16);
        int kb = s * 32;
#pragma unroll
        for (int nt = 0; nt < 16; nt++) {
            const char* bh = Wh + (nt * 8 + g) * (TSTRIDE * 2) + tig * 4 + kb;
            const char* bl = Wl + (nt * 8 + g) * (TSTRIDE * 2) + tig * 4 + kb;
            unsigned int b0h = *(const unsigned int*)(bh);
            unsigned int b1h = *(const unsigned int*)(bh + 16);
            unsigned int b0l = *(const unsigned int*)(bl);
            unsigned int b1l = *(const unsigned int*)(bl + 16);
            float* c = acc + nt * 4;
            MMA4(c, afH, b0h, b1h);
            MMA4(c, afH, b0l, b1l);
        }
    }
}

// fp32 [128 rows] tile -> fp16 smem tile (256 threads)
__device__ __forceinline__ void conv_tileH(char* hi, const float* __restrict__ src,
                                           int row0, int n, int tid) {
#pragma unroll
    for (int i = 0; i < 8; i++) {
        int ch = tid + 256 * i;
        int row = ch >> 4, part = ch & 15;
        int gr = row0 + row;
        float4 v0 = make_float4(0.f, 0.f, 0.f, 0.f);
        float4 v1 = make_float4(0.f, 0.f, 0.f, 0.f);
        if (gr < n) {
            const float4* p = (const float4*)(src + gr * DD + part * 8);
            v0 = __ldg(p);
            v1 = __ldg(p + 1);
        }
        float s[8];
        s[0] = v0.x; s[1] = v0.y; s[2] = v0.z; s[3] = v0.w;
        s[4] = v1.x; s[5] = v1.y; s[6] = v1.z; s[7] = v1.w;
        union { uint4 u; __half h[8]; } H;
#pragma unroll
        for (int j = 0; j < 8; j++) H.h[j] = __float2half_rn(s[j]);
        int off = (row * TSTRIDE + part * 8) * 2;
        *(uint4*)(hi + off) = H.u;
    }
}

// fp16 [128 rows] tile -> fp16 smem tile (plain strided copy, 256 threads)
__device__ __forceinline__ void copy_tileH(char* hi, const __half* __restrict__ src,
                                           int row0, int n, int tid) {
#pragma unroll
    for (int i = 0; i < 8; i++) {
        int ch = tid + 256 * i;
        int row = ch >> 4, part = ch & 15;
        int gr = row0 + row;
        uint4 v = make_uint4(0u, 0u, 0u, 0u);
        if (gr < n) v = __ldg((const uint4*)(src + gr * DD + part * 8));
        int off = (row * TSTRIDE + part * 8) * 2;
        *(uint4*)(hi + off) = v;
    }
}

// full weight tile pair global -> smem (256 threads)
__device__ __forceinline__ void load_wt256(char* hi, char* lo,
                                           const unsigned char* gh,
                                           const unsigned char* gl, int tid) {
#pragma unroll
    for (int i = 0; i < 9; i++) {
        int idx = tid + 256 * i;
        if (idx < TU4) {
            ((uint4*)hi)[idx] = __ldg((const uint4*)gh + idx);
            ((uint4*)lo)[idx] = __ldg((const uint4*)gl + idx);
        }
    }
}

// ---------------- LUT build + count zero ---------------------------------------
__global__ void k_lut_zcnt(int n) {
    int stride = blockDim.x * gridDim.x;
    for (int i = threadIdx.x + blockIdx.x * blockDim.x; i <= LUTN; i += stride) {
        float z0 = -8.f + (float)i * (16.f / LUTN);
        float z1 = z0 + (16.f / LUTN);
        float s0 = 1.f / (1.f + expf(-z0));
        float s1 = 1.f / (1.f + expf(-z1));
        float d  = s1 - s0;
        g_lut[i] = make_float2(s0 - (float)i * d, d);
    }
    for (int i = threadIdx.x + blockIdx.x * blockDim.x; i < n; i += stride)
        g_cnti[i] = 0;
}

// ---------------- fused: degree count + weight prep -----------------------------
__global__ void k_count_wprep(const int* __restrict__ ei, int E,
                              const float* __restrict__ aggW, const float* __restrict__ uW1,
                              const float* __restrict__ uW2, const float* __restrict__ resW) {
    int tid0 = threadIdx.x + blockIdx.x * blockDim.x;
    int stride = blockDim.x * gridDim.x;
    for (int idx = tid0; idx < 5 * 16384; idx += stride) {
        int mat = idx >> 14, e = idx & 16383;
        int k = e >> 7, col = e & 127;
        const float* src = (mat == 0) ? aggW : (mat == 1) ? uW1 : (mat == 2) ? (uW1 + 16384)
                         : (mat == 3) ? uW2 : resW;
        float v = __ldg(&src[k * DD + col]);
        __half h = __float2half_rn(v);
        __half l = __float2half_rn(v - __half2float(h));
        int off = (col * TSTRIDE + k) * 2;
        *(__half*)(&g_wt[mat][0][off]) = h;
        *(__half*)(&g_wt[mat][1][off]) = l;
    }
    for (int i = tid0; i < E; i += stride)
        atomicAdd(&g_cnti[__ldg(&ei[E + i])], 1);
}

__global__ void __launch_bounds__(1024)
k_scan_fused(int n, int E) {
    __shared__ int sh[1024];
    int t = threadIdx.x;
    int len = (n + 1023) / 1024;
    int s = t * len;
    int e = min(s + len, n);
    int sum = 0;
    for (int i = s; i < e; i++) sum += g_cnti[i];
    sh[t] = sum;
    __syncthreads();
    for (int o = 1; o < 1024; o <<= 1) {
        int u = (t >= o) ? sh[t - o] : 0;
        __syncthreads();
        sh[t] += u;
        __syncthreads();
    }
    int excl = sh[t] - sum;
    for (int i = s; i < e; i++) {
        int c = g_cnti[i];
        g_rows[i] = excl;
        g_cur[i]  = excl;
        excl += c;
    }
    if (t == 0) g_rows[n] = E;
}

// ---------------- edge gate + CSR permute (thread per edge, tanh.approx) ---------
__global__ void __launch_bounds__(256)
k_gate(const int* __restrict__ ei, const float* __restrict__ ea,
       const float* __restrict__ W1, const float* __restrict__ b1,
       const float* __restrict__ W2, const float* __restrict__ b2p, int E) {
    __shared__ ull w1s[4][64];
    __shared__ ull b1s[64];
    __shared__ ull w2s[64];

    if (threadIdx.x < 64) {
        int c2 = threadIdx.x;
#pragma unroll
        for (int k = 0; k < 4; k++)
            w1s[k][c2] = __ldg((const ull*)(W1 + k * DD) + c2);
        b1s[c2] = __ldg((const ull*)b1 + c2);
        w2s[c2] = __ldg((const ull*)W2 + c2);
    }
    __syncthreads();

    float b2v = __ldg(b2p);
    int stride = blockDim.x * gridDim.x;
    int e0 = threadIdx.x + blockIdx.x * blockDim.x;

    int src = 0, dst = 0;
    float4 a = make_float4(0.f, 0.f, 0.f, 0.f);
    if (e0 < E) {
        src = __ldg(&ei[e0]);
        dst = __ldg(&ei[E + e0]);
        a   = __ldg((const float4*)(ea + 4 * e0));
    }

    for (int e = e0; e < E; ) {
        int srcC = src, dstC = dst;
        float4 aC = a;
        int eN = e + stride;
        if (eN < E) {
            src = __ldg(&ei[eN]);
            dst = __ldg(&ei[E + eN]);
            a   = __ldg((const float4*)(ea + 4 * eN));
        }

        ull ax = pack_dup(aC.x), ay = pack_dup(aC.y);
        ull az = pack_dup(aC.z), aw = pack_dup(aC.w);
        ull dot2 = 0ull;
#pragma unroll 16
        for (int c2 = 0; c2 < 64; c2++) {
            ull zz = b1s[c2];
            fma2(zz, ax, w1s[0][c2]);
            fma2(zz, ay, w1s[1][c2]);
            fma2(zz, az, w1s[2][c2]);
            fma2(zz, aw, w1s[3][c2]);
            float z0, z1;
            unpack2(zz, z0, z1);
            float s0 = z0 * sig_t(z0);     // silu via tanh.approx
            float s1 = z1 * sig_t(z1);
            fma2(dot2, pack2(s0, s1), w2s[c2]);
        }
        float d0, d1;
        unpack2(dot2, d0, d1);
        float ew = sig_t(d0 + d1 + b2v);

        int pos = atomicAdd(&g_cur[dstC], 1);
        g_csr_src[pos] = srcC;
        g_csr_w[pos]   = ew;
        e = eN;
    }
}

// ---------------- gather (warp per node, fp16 messages) --------------------------
__device__ __forceinline__ void acc_half4(float4& a, unsigned int lo, unsigned int hi, float w) {
    float2 f0 = __half22float2(*(__half2*)&lo);
    float2 f1 = __half22float2(*(__half2*)&hi);
    a.x = fmaf(w, f0.x, a.x); a.y = fmaf(w, f0.y, a.y);
    a.z = fmaf(w, f1.x, a.z); a.w = fmaf(w, f1.y, a.w);
}

__global__ void __launch_bounds__(256)
k_gather(int n) {
    int lane  = threadIdx.x & 31;
    int w     = (blockIdx.x * blockDim.x + threadIdx.x) >> 5;
    int nwarp = (gridDim.x * blockDim.x) >> 5;

    for (int i = w; i < n; i += nwarp) {
        int s = g_rows[i], e = g_rows[i + 1];
        float4 a0 = make_float4(0.f, 0.f, 0.f, 0.f);
        float4 a1 = make_float4(0.f, 0.f, 0.f, 0.f);
        float4 a2 = make_float4(0.f, 0.f, 0.f, 0.f);
        float4 a3 = make_float4(0.f, 0.f, 0.f, 0.f);
        int j = s;
        for (; j + 3 < e; j += 4) {
            int   s0 = __ldg(&g_csr_src[j]);
            int   s1 = __ldg(&g_csr_src[j + 1]);
            int   s2 = __ldg(&g_csr_src[j + 2]);
            int   s3 = __ldg(&g_csr_src[j + 3]);
            float w0 = __ldg(&g_csr_w[j]);
            float w1 = __ldg(&g_csr_w[j + 1]);
            float w2 = __ldg(&g_csr_w[j + 2]);
            float w3 = __ldg(&g_csr_w[j + 3]);
            uint2 v0 = __ldg((const uint2*)(g_ax + s0 * DD + lane * 4));
            uint2 v1 = __ldg((const uint2*)(g_ax + s1 * DD + lane * 4));
            uint2 v2 = __ldg((const uint2*)(g_ax + s2 * DD + lane * 4));
            uint2 v3 = __ldg((const uint2*)(g_ax + s3 * DD + lane * 4));
            acc_half4(a0, v0.x, v0.y, w0);
            acc_half4(a1, v1.x, v1.y, w1);
            acc_half4(a2, v2.x, v2.y, w2);
            acc_half4(a3, v3.x, v3.y, w3);
        }
        for (; j < e; j++) {
            int   s0 = __ldg(&g_csr_src[j]);
            float w0 = __ldg(&g_csr_w[j]);
            uint2 v0 = __ldg((const uint2*)(g_ax + s0 * DD + lane * 4));
            acc_half4(a0, v0.x, v0.y, w0);
        }
        float rv = 1.f / fmaxf((float)(e - s), 1.f);
        float ox = (a0.x + a1.x + a2.x + a3.x) * rv;
        float oy = (a0.y + a1.y + a2.y + a3.y) * rv;
        float oz = (a0.z + a1.z + a2.z + a3.z) * rv;
        float ow = (a0.w + a1.w + a2.w + a3.w) * rv;
        union { uint2 u; __half h[4]; } O;
        O.h[0] = __float2half_rn(ox); O.h[1] = __float2half_rn(oy);
        O.h[2] = __float2half_rn(oz); O.h[3] = __float2half_rn(ow);
        *(uint2*)(g_agg + i * DD + lane * 4) = O.u;
    }
}

// ---------------- K1 (HMMA fp16): g_ax = silu(x @ agg_W + b) ---------------------
// smem: bias 512 + AH + WH + WL = 512 + 3*34816 = 104960 -> 2 blocks/SM
__global__ void __launch_bounds__(256, 2)
k_agg_m(const float* __restrict__ x, const float* __restrict__ bias, int n) {
    extern __shared__ char sm[];
    const int O_B = 0, O_AH = 512, O_WH = O_AH + TBYTES, O_WL = O_WH + TBYTES;
    int tid = threadIdx.x;
    int row0 = blockIdx.x * 128;

    if (tid < 128) ((float*)(sm + O_B))[tid] = __ldg(&bias[tid]);
    conv_tileH(sm + O_AH, x, row0, n, tid);
    load_wt256(sm + O_WH, sm + O_WL, g_wt[0][0], g_wt[0][1], tid);
    __syncthreads();

    int lane = tid & 31, warp = tid >> 5;
    int g = lane >> 2, tig = lane & 3;

    float acc[64];
#pragma unroll
    for (int i = 0; i < 64; i++) acc[i] = 0.f;
    mma_span(acc, sm + O_AH, sm + O_WH, sm + O_WL, 0, 8, warp, g, tig);

    const float* bs = (const float*)(sm + O_B);
    int r_hi = row0 + warp * 16 + g;
    int r_lo = r_hi + 8;
#pragma unroll
    for (int nt = 0; nt < 16; nt++) {
        int c0 = nt * 8 + tig * 2;
        float b0 = bs[c0], b1v = bs[c0 + 1];
        if (r_hi < n) {
            float z0 = acc[nt * 4 + 0] + b0, z1 = acc[nt * 4 + 1] + b1v;
            __half2 v = __floats2half2_rn(z0 * lut_sigma_g(z0), z1 * lut_sigma_g(z1));
            *(__half2*)(g_ax + r_hi * DD + c0) = v;
        }
        if (r_lo < n) {
            float z0 = acc[nt * 4 + 2] + b0, z1 = acc[nt * 4 + 3] + b1v;
            __half2 v = __floats2half2_rn(z0 * lut_sigma_g(z0), z1 * lut_sigma_g(z1));
            *(__half2*)(g_ax + r_lo * DD + c0) = v;
        }
    }
}

// ---------------- fused update (HMMA fp16): 4 chained GEMMs + LN -----------------
// smem: params 2048 + XH, TH, WH, WL = 2048 + 4*34816 = 141312
__global__ void __launch_bounds__(256)
k_upd12_m(const float* __restrict__ x,
          const float* __restrict__ b1, const float* __restrict__ b2,
          const float* __restrict__ lng, const float* __restrict__ lnb,
          float* __restrict__ out, int n) {
    extern __shared__ char sm[];
    const int O_B1 = 0, O_B2 = 512, O_LG = 1024, O_LB = 1536,
              O_XH = 2048, O_TH = O_XH + TBYTES,
              O_WH = O_TH + TBYTES, O_WL = O_WH + TBYTES;
    int tid = threadIdx.x;
    int row0 = blockIdx.x * 128;

    if (tid < 128) {
        ((float*)(sm + O_B1))[tid] = __ldg(&b1[tid]);
        ((float*)(sm + O_B2))[tid] = __ldg(&b2[tid]);
        ((float*)(sm + O_LG))[tid] = __ldg(&lng[tid]);
        ((float*)(sm + O_LB))[tid] = __ldg(&lnb[tid]);
    }
    conv_tileH(sm + O_XH, x, row0, n, tid);
    copy_tileH(sm + O_TH, g_agg, row0, n, tid);
    load_wt256(sm + O_WH, sm + O_WL, g_wt[1][0], g_wt[1][1], tid);
    __syncthreads();

    int lane = tid & 31, warp = tid >> 5;
    int g = lane >> 2, tig = lane & 3;

    float acc[64];
#pragma unroll
    for (int i = 0; i < 64; i++) acc[i] = 0.f;

    // phase A: x @ W1a
    mma_span(acc, sm + O_XH, sm + O_WH, sm + O_WL, 0, 8, warp, g, tig);
    __syncthreads();

    // phase B: agg @ W1b
    load_wt256(sm + O_WH, sm + O_WL, g_wt[2][0], g_wt[2][1], tid);
    __syncthreads();
    mma_span(acc, sm + O_TH, sm + O_WH, sm + O_WL, 0, 8, warp, g, tig);
    __syncthreads();

    // h1 = silu(acc + b1) -> fp16 back into T tile; load W2
    {
        const float* b1s = (const float*)(sm + O_B1);
        int r_hi = warp * 16 + g;
#pragma unroll
        for (int nt = 0; nt < 16; nt++) {
            int c0 = nt * 8 + tig * 2;
            float bb0 = b1s[c0], bb1 = b1s[c0 + 1];
#pragma unroll
            for (int half = 0; half < 2; half++) {
                int r = r_hi + half * 8;
                float z0 = acc[nt * 4 + half * 2 + 0] + bb0;
                float z1 = acc[nt * 4 + half * 2 + 1] + bb1;
                float v0 = z0 * lut_sigma_g(z0);
                float v1 = z1 * lut_sigma_g(z1);
                __half h0 = __float2half_rn(v0);
                __half h1 = __float2half_rn(v1);
                unsigned int hp = ((unsigned int)__half_as_ushort(h1) << 16)
                                | __half_as_ushort(h0);
                int off = (r * TSTRIDE + c0) * 2;
                *(unsigned int*)(sm + O_TH + off) = hp;
            }
        }
        load_wt256(sm + O_WH, sm + O_WL, g_wt[3][0], g_wt[3][1], tid);
    }
    __syncthreads();

    // phase C: h1 @ W2
#pragma unroll
    for (int i = 0; i < 64; i++) acc[i] = 0.f;
    mma_span(acc, sm + O_TH, sm + O_WH, sm + O_WL, 0, 8, warp, g, tig);
    __syncthreads();

    // phase D: x @ resW
    load_wt256(sm + O_WH, sm + O_WL, g_wt[4][0], g_wt[4][1], tid);
    __syncthreads();
    mma_span(acc, sm + O_XH, sm + O_WH, sm + O_WL, 0, 8, warp, g, tig);

    // epilogue: z = acc + b2, per-row LayerNorm via quad reduction
    {
        const float* b2s = (const float*)(sm + O_B2);
        const float* lg  = (const float*)(sm + O_LG);
        const float* lb  = (const float*)(sm + O_LB);

        float sA = 0.f, qA = 0.f, sB = 0.f, qB = 0.f;
#pragma unroll
        for (int nt = 0; nt < 16; nt++) {
            int c0 = nt * 8 + tig * 2;
            float bb0 = b2s[c0], bb1 = b2s[c0 + 1];
            float z0 = acc[nt * 4 + 0] + bb0, z1 = acc[nt * 4 + 1] + bb1;
            float z2 = acc[nt * 4 + 2] + bb0, z3 = acc[nt * 4 + 3] + bb1;
            acc[nt * 4 + 0] = z0; acc[nt * 4 + 1] = z1;
            acc[nt * 4 + 2] = z2; acc[nt * 4 + 3] = z3;
            sA += z0 + z1; qA += z0 * z0 + z1 * z1;
            sB += z2 + z3; qB += z2 * z2 + z3 * z3;
        }
#pragma unroll
        for (int m = 1; m <= 2; m <<= 1) {
            sA += __shfl_xor_sync(0xffffffffu, sA, m);
            qA += __shfl_xor_sync(0xffffffffu, qA, m);
            sB += __shfl_xor_sync(0xffffffffu, sB, m);
            qB += __shfl_xor_sync(0xffffffffu, qB, m);
        }
        float muA = sA * (1.f / 128.f);
        float rsA = rsqrtf(qA * (1.f / 128.f) - muA * muA + LNEPS);
        float muB = sB * (1.f / 128.f);
        float rsB = rsqrtf(qB * (1.f / 128.f) - muB * muB + LNEPS);

        int r_hi = row0 + warp * 16 + g;
        int r_lo = r_hi + 8;
#pragma unroll
        for (int nt = 0; nt < 16; nt++) {
            int c0 = nt * 8 + tig * 2;
            float g0 = lg[c0], g1 = lg[c0 + 1];
            float o0 = lb[c0], o1 = lb[c0 + 1];
            if (r_hi < n) {
                float2 v;
                v.x = (acc[nt * 4 + 0] - muA) * rsA * g0 + o0;
                v.y = (acc[nt * 4 + 1] - muA) * rsA * g1 + o1;
                *(float2*)(out + r_hi * DD + c0) = v;
            }
            if (r_lo < n) {
                float2 v;
                v.x = (acc[nt * 4 + 2] - muB) * rsB * g0 + o0;
                v.y = (acc[nt * 4 + 3] - muB) * rsB * g1 + o1;
                *(float2*)(out + r_lo * DD + c0) = v;
            }
        }
    }
}

// ---------------- launch -----------------------------------------------------------
extern "C" void kernel_launch(void* const* d_in, const int* in_sizes, int n_in,
                              void* d_out, int out_size) {
    const float* x    = (const float*)d_in[0];
    const int*   ei   = (const int*)  d_in[1];
    const float* ea   = (const float*)d_in[2];
    const float* aggW = (const float*)d_in[3];
    const float* aggb = (const float*)d_in[4];
    const float* eW1  = (const float*)d_in[5];
    const float* eb1  = (const float*)d_in[6];
    const float* eW2  = (const float*)d_in[7];
    const float* eb2  = (const float*)d_in[8];
    const float* uW1  = (const float*)d_in[9];
    const float* ub1  = (const float*)d_in[10];
    const float* uW2  = (const float*)d_in[11];
    const float* ub2  = (const float*)d_in[12];
    const float* lng  = (const float*)d_in[13];
    const float* lnb  = (const float*)d_in[14];
    const float* resW = (const float*)d_in[15];

    int n = in_sizes[0] / DD;
    int E = in_sizes[2] / 4;

    const int SMEM_A = 512 + 3 * TBYTES;    // 104960 -> 2 blocks/SM
    const int SMEM_U = 2048 + 4 * TBYTES;   // 141312
    cudaFuncSetAttribute(k_agg_m,   cudaFuncAttributeMaxDynamicSharedMemorySize, SMEM_A);
    cudaFuncSetAttribute(k_upd12_m, cudaFuncAttributeMaxDynamicSharedMemorySize, SMEM_U);

    int gblocks = (n + 127) / 128;   // 782

    // 4th launch (k_gate) is the profiled one -> verify tanh.approx effect
    k_lut_zcnt<<<512, 256>>>(n);                                        // 1
    k_count_wprep<<<1024, 256>>>(ei, E, aggW, uW1, uW2, resW);          // 2
    k_scan_fused<<<1, 1024>>>(n, E);                                    // 3
    k_gate<<<888, 256>>>(ei, ea, eW1, eb1, eW2, eb2, E);                // 4 <- profiled
    k_agg_m<<<gblocks, 256, SMEM_A>>>(x, aggb, n);                      // 5
    k_gather<<<2048, 256>>>(n);                                         // 6
    k_upd12_m<<<gblocks, 256, SMEM_U>>>(x, ub1, ub2, lng, lnb,
                                        (float*)d_out, n);              // 7
}

// round 17
// speedup vs baseline: 1.7012x; 1.0081x over previous
#include <cuda_runtime.h>
#include <cuda_fp16.h>
#include <cstdint>
#include <math.h>

#define DD 128
#define NMAX 100000
#define EMAX 1600000
#define LNEPS 1e-5f
#define TSTRIDE 136                    // fp16 elems per smem tile row (bank-safe)
#define TBYTES (128 * TSTRIDE * 2)     // 34816 B per 128x128 fp16 tile
#define TU4 (TBYTES / 16)

typedef unsigned long long ull;

// ---------------- scratch (static device globals) ---------------------------
__device__ __half g_ax[NMAX * DD];     // silu(x @ agg_W + b), fp16
__device__ __half g_agg[NMAX * DD];    // mean-aggregated messages, fp16
__device__ int    g_cnti[NMAX];        // zero-init; reset by k_scan_fused each run
__device__ int    g_rows[NMAX + 1];
__device__ int    g_cur[NMAX];
__device__ int    g_csr_src[EMAX];
__device__ float  g_csr_w[EMAX];
// pre-split transposed fp16 weights, [N rows][K cols] stride TSTRIDE:
// mats: 0=aggW, 1=uW1[:128], 2=uW1[128:], 3=uW2, 4=resW
__device__ __align__(16) unsigned char g_wt[5][2][TBYTES];

// ---------------- packed f32x2 helpers (gate kernel) --------------------------
__device__ __forceinline__ ull pack_dup(float a) {
    unsigned int au = __float_as_uint(a);
    ull r; asm("mov.b64 %0, {%1, %1};" : "=l"(r) : "r"(au)); return r;
}
__device__ __forceinline__ ull pack2(float lo, float hi) {
    ull r; asm("mov.b64 %0, {%1, %2};" : "=l"(r) : "r"(__float_as_uint(lo)), "r"(__float_as_uint(hi))); return r;
}
__device__ __forceinline__ void fma2(ull& d, ull a, ull b) {
    asm("fma.rn.f32x2 %0, %1, %2, %0;" : "+l"(d) : "l"(a), "l"(b));
}
__device__ __forceinline__ void unpack2(ull v, float& lo, float& hi) {
    unsigned int l, h;
    asm("mov.b64 {%0, %1}, %2;" : "=r"(l), "=r"(h) : "l"(v));
    lo = __uint_as_float(l); hi = __uint_as_float(h);
}
__device__ __forceinline__ float tanhap(float x) {
    float r;
    asm("tanh.approx.f32 %0, %1;" : "=f"(r) : "f"(x));
    return r;
}
// sigmoid via 1 MUFU: 0.5 + 0.5*tanh(z/2)
__device__ __forceinline__ float sig_t(float z) {
    return fmaf(tanhap(z * 0.5f), 0.5f, 0.5f);
}

// ---------------- fp16 mma.sync (sm_70+ baseline) ------------------------------
#define MMA4(c, a, b0, b1) \
    asm volatile("mma.sync.aligned.m16n8k16.row.col.f32.f16.f16.f32 " \
        "{%0,%1,%2,%3}, {%4,%5,%6,%7}, {%8,%9}, {%0,%1,%2,%3};" \
        : "+f"((c)[0]), "+f"((c)[1]), "+f"((c)[2]), "+f"((c)[3]) \
        : "r"((a)[0]), "r"((a)[1]), "r"((a)[2]), "r"((a)[3]), "r"(b0), "r"(b1))

__device__ __forceinline__ unsigned int h2u(float lo, float hi) {
    __half2 h = __floats2half2_rn(lo, hi);
    return *(unsigned int*)&h;
}

// GEMM span with A fragments from SMEM (fp16 tile)
__device__ __forceinline__ void mma_span(float* acc,
    const char* Ah, const char* Wh, const char* Wl,
    int warp, int g, int tig) {
    const char* arow = Ah + ((warp * 16 + g) * TSTRIDE + tig * 2) * 2;
#pragma unroll
    for (int s = 0; s < 8; s++) {
        unsigned int afH[4];
        const char* pa = arow + s * 32;
        afH[0] = *(const unsigned int*)(pa);
        afH[1] = *(const unsigned int*)(pa + 8 * TSTRIDE * 2);
        afH[2] = *(const unsigned int*)(pa + 16);
        afH[3] = *(const unsigned int*)(pa + 8 * TSTRIDE * 2 + 16);
        int kb = s * 32;
#pragma unroll
        for (int nt = 0; nt < 16; nt++) {
            const char* bh = Wh + (nt * 8 + g) * (TSTRIDE * 2) + tig * 4 + kb;
            const char* bl = Wl + (nt * 8 + g) * (TSTRIDE * 2) + tig * 4 + kb;
            unsigned int b0h = *(const unsigned int*)(bh);
            unsigned int b1h = *(const unsigned int*)(bh + 16);
            unsigned int b0l = *(const unsigned int*)(bl);
            unsigned int b1l = *(const unsigned int*)(bl + 16);
            float* c = acc + nt * 4;
            MMA4(c, afH, b0h, b1h);
            MMA4(c, afH, b0l, b1l);
        }
    }
}

// GEMM span with A fragments loaded DIRECTLY from global fp32 x (no smem tile)
__device__ __forceinline__ void mma_span_gx(float* acc,
    const float* __restrict__ x, int row0, int n,
    const char* Wh, const char* Wl,
    int warp, int g, int tig) {
    int r0 = row0 + warp * 16 + g;
    int r1 = r0 + 8;
    const float* p0 = x + r0 * DD;
    const float* p1 = x + r1 * DD;
    bool v0 = r0 < n, v1 = r1 < n;
    float2 zz2 = make_float2(0.f, 0.f);
#pragma unroll
    for (int s = 0; s < 8; s++) {
        int k0 = s * 16 + tig * 2;
        float2 a00 = v0 ? __ldg((const float2*)(p0 + k0))     : zz2;
        float2 a01 = v0 ? __ldg((const float2*)(p0 + k0 + 8)) : zz2;
        float2 a10 = v1 ? __ldg((const float2*)(p1 + k0))     : zz2;
        float2 a11 = v1 ? __ldg((const float2*)(p1 + k0 + 8)) : zz2;
        unsigned int afH[4];
        afH[0] = h2u(a00.x, a00.y);
        afH[1] = h2u(a10.x, a10.y);
        afH[2] = h2u(a01.x, a01.y);
        afH[3] = h2u(a11.x, a11.y);
        int kb = s * 32;
#pragma unroll
        for (int nt = 0; nt < 16; nt++) {
            const char* bh = Wh + (nt * 8 + g) * (TSTRIDE * 2) + tig * 4 + kb;
            const char* bl = Wl + (nt * 8 + g) * (TSTRIDE * 2) + tig * 4 + kb;
            unsigned int b0h = *(const unsigned int*)(bh);
            unsigned int b1h = *(const unsigned int*)(bh + 16);
            unsigned int b0l = *(const unsigned int*)(bl);
            unsigned int b1l = *(const unsigned int*)(bl + 16);
            float* c = acc + nt * 4;
            MMA4(c, afH, b0h, b1h);
            MMA4(c, afH, b0l, b1l);
        }
    }
}

// fp16 [128 rows] tile -> fp16 smem tile (plain strided copy, 256 threads)
__device__ __forceinline__ void copy_tileH(char* hi, const __half* __restrict__ src,
                                           int row0, int n, int tid) {
#pragma unroll
    for (int i = 0; i < 8; i++) {
        int ch = tid + 256 * i;
        int row = ch >> 4, part = ch & 15;
        int gr = row0 + row;
        uint4 v = make_uint4(0u, 0u, 0u, 0u);
        if (gr < n) v = __ldg((const uint4*)(src + gr * DD + part * 8));
        int off = (row * TSTRIDE + part * 8) * 2;
        *(uint4*)(hi + off) = v;
    }
}

// full weight tile pair global -> smem (256 threads)
__device__ __forceinline__ void load_wt256(char* hi, char* lo,
                                           const unsigned char* gh,
                                           const unsigned char* gl, int tid) {
#pragma unroll
    for (int i = 0; i < 9; i++) {
        int idx = tid + 256 * i;
        if (idx < TU4) {
            ((uint4*)hi)[idx] = __ldg((const uint4*)gh + idx);
            ((uint4*)lo)[idx] = __ldg((const uint4*)gl + idx);
        }
    }
}

// ---------------- fused: degree count + weight prep -----------------------------
__global__ void k_count_wprep(const int* __restrict__ ei, int E,
                              const float* __restrict__ aggW, const float* __restrict__ uW1,
                              const float* __restrict__ uW2, const float* __restrict__ resW) {
    int tid0 = threadIdx.x + blockIdx.x * blockDim.x;
    int stride = blockDim.x * gridDim.x;
    for (int idx = tid0; idx < 5 * 16384; idx += stride) {
        int mat = idx >> 14, e = idx & 16383;
        int k = e >> 7, col = e & 127;
        const float* src = (mat == 0) ? aggW : (mat == 1) ? uW1 : (mat == 2) ? (uW1 + 16384)
                         : (mat == 3) ? uW2 : resW;
        float v = __ldg(&src[k * DD + col]);
        __half h = __float2half_rn(v);
        __half l = __float2half_rn(v - __half2float(h));
        int off = (col * TSTRIDE + k) * 2;
        *(__half*)(&g_wt[mat][0][off]) = h;
        *(__half*)(&g_wt[mat][1][off]) = l;
    }
    for (int i = tid0; i < E; i += stride)
        atomicAdd(&g_cnti[__ldg(&ei[E + i])], 1);
}

// scan + reset counts (self-restoring across graph replays; initial state = zero-init)
__global__ void __launch_bounds__(1024)
k_scan_fused(int n, int E) {
    __shared__ int sh[1024];
    int t = threadIdx.x;
    int len = (n + 1023) / 1024;
    int s = t * len;
    int e = min(s + len, n);
    int sum = 0;
    for (int i = s; i < e; i++) sum += g_cnti[i];
    sh[t] = sum;
    __syncthreads();
    for (int o = 1; o < 1024; o <<= 1) {
        int u = (t >= o) ? sh[t - o] : 0;
        __syncthreads();
        sh[t] += u;
        __syncthreads();
    }
    int excl = sh[t] - sum;
    for (int i = s; i < e; i++) {
        int c = g_cnti[i];
        g_rows[i] = excl;
        g_cur[i]  = excl;
        g_cnti[i] = 0;             // reset for next replay
        excl += c;
    }
    if (t == 0) g_rows[n] = E;
}

// ---------------- edge gate + CSR permute (thread per edge, tanh.approx) ---------
__global__ void __launch_bounds__(256)
k_gate(const int* __restrict__ ei, const float* __restrict__ ea,
       const float* __restrict__ W1, const float* __restrict__ b1,
       const float* __restrict__ W2, const float* __restrict__ b2p, int E) {
    __shared__ ull w1s[4][64];
    __shared__ ull b1s[64];
    __shared__ ull w2s[64];

    if (threadIdx.x < 64) {
        int c2 = threadIdx.x;
#pragma unroll
        for (int k = 0; k < 4; k++)
            w1s[k][c2] = __ldg((const ull*)(W1 + k * DD) + c2);
        b1s[c2] = __ldg((const ull*)b1 + c2);
        w2s[c2] = __ldg((const ull*)W2 + c2);
    }
    __syncthreads();

    float b2v = __ldg(b2p);
    int stride = blockDim.x * gridDim.x;
    int e0 = threadIdx.x + blockIdx.x * blockDim.x;

    int src = 0, dst = 0;
    float4 a = make_float4(0.f, 0.f, 0.f, 0.f);
    if (e0 < E) {
        src = __ldg(&ei[e0]);
        dst = __ldg(&ei[E + e0]);
        a   = __ldg((const float4*)(ea + 4 * e0));
    }

    for (int e = e0; e < E; ) {
        int srcC = src, dstC = dst;
        float4 aC = a;
        int eN = e + stride;
        if (eN < E) {
            src = __ldg(&ei[eN]);
            dst = __ldg(&ei[E + eN]);
            a   = __ldg((const float4*)(ea + 4 * eN));
        }

        ull ax = pack_dup(aC.x), ay = pack_dup(aC.y);
        ull az = pack_dup(aC.z), aw = pack_dup(aC.w);
        ull dot2 = 0ull;
#pragma unroll 16
        for (int c2 = 0; c2 < 64; c2++) {
            ull zz = b1s[c2];
            fma2(zz, ax, w1s[0][c2]);
            fma2(zz, ay, w1s[1][c2]);
            fma2(zz, az, w1s[2][c2]);
            fma2(zz, aw, w1s[3][c2]);
            float z0, z1;
            unpack2(zz, z0, z1);
            float s0 = z0 * sig_t(z0);
            float s1 = z1 * sig_t(z1);
            fma2(dot2, pack2(s0, s1), w2s[c2]);
        }
        float d0, d1;
        unpack2(dot2, d0, d1);
        float ew = sig_t(d0 + d1 + b2v);

        int pos = atomicAdd(&g_cur[dstC], 1);
        g_csr_src[pos] = srcC;
        g_csr_w[pos]   = ew;
        e = eN;
    }
}

// ---------------- K1 (HMMA fp16): g_ax = silu(x @ agg_W + b) ---------------------
// smem: bias 512 + WH + WL = 70144 -> 2 blocks/SM (reg-limited)
__global__ void __launch_bounds__(256, 2)
k_agg_m(const float* __restrict__ x, const float* __restrict__ bias, int n) {
    extern __shared__ char sm[];
    const int O_B = 0, O_WH = 512, O_WL = O_WH + TBYTES;
    int tid = threadIdx.x;
    int row0 = blockIdx.x * 128;

    if (tid < 128) ((float*)(sm + O_B))[tid] = __ldg(&bias[tid]);
    load_wt256(sm + O_WH, sm + O_WL, g_wt[0][0], g_wt[0][1], tid);
    __syncthreads();

    int lane = tid & 31, warp = tid >> 5;
    int g = lane >> 2, tig = lane & 3;

    float acc[64];
#pragma unroll
    for (int i = 0; i < 64; i++) acc[i] = 0.f;
    mma_span_gx(acc, x, row0, n, sm + O_WH, sm + O_WL, warp, g, tig);

    const float* bs = (const float*)(sm + O_B);
    int r_hi = row0 + warp * 16 + g;
    int r_lo = r_hi + 8;
#pragma unroll
    for (int nt = 0; nt < 16; nt++) {
        int c0 = nt * 8 + tig * 2;
        float b0 = bs[c0], b1v = bs[c0 + 1];
        if (r_hi < n) {
            float z0 = acc[nt * 4 + 0] + b0, z1 = acc[nt * 4 + 1] + b1v;
            __half2 v = __floats2half2_rn(z0 * sig_t(z0), z1 * sig_t(z1));
            *(__half2*)(g_ax + r_hi * DD + c0) = v;
        }
        if (r_lo < n) {
            float z0 = acc[nt * 4 + 2] + b0, z1 = acc[nt * 4 + 3] + b1v;
            __half2 v = __floats2half2_rn(z0 * sig_t(z0), z1 * sig_t(z1));
            *(__half2*)(g_ax + r_lo * DD + c0) = v;
        }
    }
}

// ---------------- gather (warp per node, fp16 messages) --------------------------
__device__ __forceinline__ void acc_half4(float4& a, unsigned int lo, unsigned int hi, float w) {
    float2 f0 = __half22float2(*(__half2*)&lo);
    float2 f1 = __half22float2(*(__half2*)&hi);
    a.x = fmaf(w, f0.x, a.x); a.y = fmaf(w, f0.y, a.y);
    a.z = fmaf(w, f1.x, a.z); a.w = fmaf(w, f1.y, a.w);
}

__global__ void __launch_bounds__(256)
k_gather(int n) {
    int lane  = threadIdx.x & 31;
    int w     = (blockIdx.x * blockDim.x + threadIdx.x) >> 5;
    int nwarp = (gridDim.x * blockDim.x) >> 5;

    for (int i = w; i < n; i += nwarp) {
        int s = g_rows[i], e = g_rows[i + 1];
        float4 a0 = make_float4(0.f, 0.f, 0.f, 0.f);
        float4 a1 = make_float4(0.f, 0.f, 0.f, 0.f);
        float4 a2 = make_float4(0.f, 0.f, 0.f, 0.f);
        float4 a3 = make_float4(0.f, 0.f, 0.f, 0.f);
        int j = s;
        for (; j + 3 < e; j += 4) {
            int   s0 = __ldg(&g_csr_src[j]);
            int   s1 = __ldg(&g_csr_src[j + 1]);
            int   s2 = __ldg(&g_csr_src[j + 2]);
            int   s3 = __ldg(&g_csr_src[j + 3]);
            float w0 = __ldg(&g_csr_w[j]);
            float w1 = __ldg(&g_csr_w[j + 1]);
            float w2 = __ldg(&g_csr_w[j + 2]);
            float w3 = __ldg(&g_csr_w[j + 3]);
            uint2 v0 = __ldg((const uint2*)(g_ax + s0 * DD + lane * 4));
            uint2 v1 = __ldg((const uint2*)(g_ax + s1 * DD + lane * 4));
            uint2 v2 = __ldg((const uint2*)(g_ax + s2 * DD + lane * 4));
            uint2 v3 = __ldg((const uint2*)(g_ax + s3 * DD + lane * 4));
            acc_half4(a0, v0.x, v0.y, w0);
            acc_half4(a1, v1.x, v1.y, w1);
            acc_half4(a2, v2.x, v2.y, w2);
            acc_half4(a3, v3.x, v3.y, w3);
        }
        for (; j < e; j++) {
            int   s0 = __ldg(&g_csr_src[j]);
            float w0 = __ldg(&g_csr_w[j]);
            uint2 v0 = __ldg((const uint2*)(g_ax + s0 * DD + lane * 4));
            acc_half4(a0, v0.x, v0.y, w0);
        }
        float rv = 1.f / fmaxf((float)(e - s), 1.f);
        float ox = (a0.x + a1.x + a2.x + a3.x) * rv;
        float oy = (a0.y + a1.y + a2.y + a3.y) * rv;
        float oz = (a0.z + a1.z + a2.z + a3.z) * rv;
        float ow = (a0.w + a1.w + a2.w + a3.w) * rv;
        union { uint2 u; __half h[4]; } O;
        O.h[0] = __float2half_rn(ox); O.h[1] = __float2half_rn(oy);
        O.h[2] = __float2half_rn(oz); O.h[3] = __float2half_rn(ow);
        *(uint2*)(g_agg + i * DD + lane * 4) = O.u;
    }
}

// ---------------- fused update (HMMA fp16): 4 chained GEMMs + LN -----------------
// smem: params 2048 + TH + WH + WL = 106496 -> 2 blocks/SM
__global__ void __launch_bounds__(256, 2)
k_upd12_m(const float* __restrict__ x,
          const float* __restrict__ b1, const float* __restrict__ b2,
          const float* __restrict__ lng, const float* __restrict__ lnb,
          float* __restrict__ out, int n) {
    extern __shared__ char sm[];
    const int O_B1 = 0, O_B2 = 512, O_LG = 1024, O_LB = 1536,
              O_TH = 2048, O_WH = O_TH + TBYTES, O_WL = O_WH + TBYTES;
    int tid = threadIdx.x;
    int row0 = blockIdx.x * 128;

    if (tid < 128) {
        ((float*)(sm + O_B1))[tid] = __ldg(&b1[tid]);
        ((float*)(sm + O_B2))[tid] = __ldg(&b2[tid]);
        ((float*)(sm + O_LG))[tid] = __ldg(&lng[tid]);
        ((float*)(sm + O_LB))[tid] = __ldg(&lnb[tid]);
    }
    copy_tileH(sm + O_TH, g_agg, row0, n, tid);
    load_wt256(sm + O_WH, sm + O_WL, g_wt[1][0], g_wt[1][1], tid);
    __syncthreads();

    int lane = tid & 31, warp = tid >> 5;
    int g = lane >> 2, tig = lane & 3;

    float acc[64];
#pragma unroll
    for (int i = 0; i < 64; i++) acc[i] = 0.f;

    // phase A: x @ W1a (A from global)
    mma_span_gx(acc, x, row0, n, sm + O_WH, sm + O_WL, warp, g, tig);
    __syncthreads();

    // phase B: agg @ W1b (A from TH)
    load_wt256(sm + O_WH, sm + O_WL, g_wt[2][0], g_wt[2][1], tid);
    __syncthreads();
    mma_span(acc, sm + O_TH, sm + O_WH, sm + O_WL, warp, g, tig);
    __syncthreads();

    // h1 = silu(acc + b1) -> fp16 back into TH; load W2
    {
        const float* b1s = (const float*)(sm + O_B1);
        int r_hi = warp * 16 + g;
#pragma unroll
        for (int nt = 0; nt < 16; nt++) {
            int c0 = nt * 8 + tig * 2;
            float bb0 = b1s[c0], bb1 = b1s[c0 + 1];
#pragma unroll
            for (int half = 0; half < 2; half++) {
                int r = r_hi + half * 8;
                float z0 = acc[nt * 4 + half * 2 + 0] + bb0;
                float z1 = acc[nt * 4 + half * 2 + 1] + bb1;
                float v0 = z0 * sig_t(z0);
                float v1 = z1 * sig_t(z1);
                int off = (r * TSTRIDE + c0) * 2;
                *(unsigned int*)(sm + O_TH + off) = h2u(v0, v1);
            }
        }
        load_wt256(sm + O_WH, sm + O_WL, g_wt[3][0], g_wt[3][1], tid);
    }
    __syncthreads();

    // phase C: h1 @ W2
#pragma unroll
    for (int i = 0; i < 64; i++) acc[i] = 0.f;
    mma_span(acc, sm + O_TH, sm + O_WH, sm + O_WL, warp, g, tig);
    __syncthreads();

    // phase D: x @ resW (A from global)
    load_wt256(sm + O_WH, sm + O_WL, g_wt[4][0], g_wt[4][1], tid);
    __syncthreads();
    mma_span_gx(acc, x, row0, n, sm + O_WH, sm + O_WL, warp, g, tig);

    // epilogue: z = acc + b2, per-row LayerNorm via quad reduction
    {
        const float* b2s = (const float*)(sm + O_B2);
        const float* lg  = (const float*)(sm + O_LG);
        const float* lb  = (const float*)(sm + O_LB);

        float sA = 0.f, qA = 0.f, sB = 0.f, qB = 0.f;
#pragma unroll
        for (int nt = 0; nt < 16; nt++) {
            int c0 = nt * 8 + tig * 2;
            float bb0 = b2s[c0], bb1 = b2s[c0 + 1];
            float z0 = acc[nt * 4 + 0] + bb0, z1 = acc[nt * 4 + 1] + bb1;
            float z2 = acc[nt * 4 + 2] + bb0, z3 = acc[nt * 4 + 3] + bb1;
            acc[nt * 4 + 0] = z0; acc[nt * 4 + 1] = z1;
            acc[nt * 4 + 2] = z2; acc[nt * 4 + 3] = z3;
            sA += z0 + z1; qA += z0 * z0 + z1 * z1;
            sB += z2 + z3; qB += z2 * z2 + z3 * z3;
        }
#pragma unroll
        for (int m = 1; m <= 2; m <<= 1) {
            sA += __shfl_xor_sync(0xffffffffu, sA, m);
            qA += __shfl_xor_sync(0xffffffffu, qA, m);
            sB += __shfl_xor_sync(0xffffffffu, sB, m);
            qB += __shfl_xor_sync(0xffffffffu, qB, m);
        }
        float muA = sA * (1.f / 128.f);
        float rsA = rsqrtf(qA * (1.f / 128.f) - muA * muA + LNEPS);
        float muB = sB * (1.f / 128.f);
        float rsB = rsqrtf(qB * (1.f / 128.f) - muB * muB + LNEPS);

        int r_hi = row0 + warp * 16 + g;
        int r_lo = r_hi + 8;
#pragma unroll
        for (int nt = 0; nt < 16; nt++) {
            int c0 = nt * 8 + tig * 2;
            float g0 = lg[c0], g1 = lg[c0 + 1];
            float o0 = lb[c0], o1 = lb[c0 + 1];
            if (r_hi < n) {
                float2 v;
                v.x = (acc[nt * 4 + 0] - muA) * rsA * g0 + o0;
                v.y = (acc[nt * 4 + 1] - muA) * rsA * g1 + o1;
                *(float2*)(out + r_hi * DD + c0) = v;
            }
            if (r_lo < n) {
                float2 v;
                v.x = (acc[nt * 4 + 2] - muB) * rsB * g0 + o0;
                v.y = (acc[nt * 4 + 3] - muB) * rsB * g1 + o1;
                *(float2*)(out + r_lo * DD + c0) = v;
            }
        }
    }
}

// ---------------- launch -----------------------------------------------------------
extern "C" void kernel_launch(void* const* d_in, const int* in_sizes, int n_in,
                              void* d_out, int out_size) {
    const float* x    = (const float*)d_in[0];
    const int*   ei   = (const int*)  d_in[1];
    const float* ea   = (const float*)d_in[2];
    const float* aggW = (const float*)d_in[3];
    const float* aggb = (const float*)d_in[4];
    const float* eW1  = (const float*)d_in[5];
    const float* eb1  = (const float*)d_in[6];
    const float* eW2  = (const float*)d_in[7];
    const float* eb2  = (const float*)d_in[8];
    const float* uW1  = (const float*)d_in[9];
    const float* ub1  = (const float*)d_in[10];
    const float* uW2  = (const float*)d_in[11];
    const float* ub2  = (const float*)d_in[12];
    const float* lng  = (const float*)d_in[13];
    const float* lnb  = (const float*)d_in[14];
    const float* resW = (const float*)d_in[15];

    int n = in_sizes[0] / DD;
    int E = in_sizes[2] / 4;

    const int SMEM_A = 512 + 2 * TBYTES;    // 70144
    const int SMEM_U = 2048 + 3 * TBYTES;   // 106496 -> 2 blocks/SM
    cudaFuncSetAttribute(k_agg_m,   cudaFuncAttributeMaxDynamicSharedMemorySize, SMEM_A);
    cudaFuncSetAttribute(k_upd12_m, cudaFuncAttributeMaxDynamicSharedMemorySize, SMEM_U);

    int gblocks = (n + 127) / 128;   // 782

    // 4th launch (k_agg_m) is the profiled one -> verify global-fragment path
    k_count_wprep<<<1024, 256>>>(ei, E, aggW, uW1, uW2, resW);          // 1
    k_scan_fused<<<1, 1024>>>(n, E);                                    // 2
    k_gate<<<888, 256>>>(ei, ea, eW1, eb1, eW2, eb2, E);                // 3
    k_agg_m<<<gblocks, 256, SMEM_A>>>(x, aggb, n);                      // 4 <- profiled
    k_gather<<<2048, 256>>>(n);                                         // 5
    k_upd12_m<<<gblocks, 256, SMEM_U>>>(x, ub1, ub2, lng, lnb,
                                        (float*)d_out, n);              // 6
}